// round 11
// baseline (speedup 1.0000x reference)
#include <cuda_runtime.h>
#include <cuda_bf16.h>
#include <cuda_fp16.h>
#include <math_constants.h>
#include <cstdint>

#define NPT 32
#define C1 128
#define C2 256
#define C3 512
#define C4 384
#define CF 768
#define KG 8
#define BMAX 1024
#define EPSF 1e-5f

// ---------------- scratch (device globals; no allocation) ----------------
__device__ float g_WfT[CF * C4];

__device__ float g_f1[BMAX * NPT * C1];
__device__ float g_p1s[BMAX * C1];
__device__ float g_p1q[BMAX * C1];
__device__ float g_bn1a[C1], g_bn1c[C1];

__device__ __half g_f1h[BMAX * NPT * C1], g_f1l[BMAX * NPT * C1];
__device__ __half g_W2h[C2 * C1], g_W2l[C2 * C1];
__device__ __half g_W3h[C3 * C3], g_W3l[C3 * C3];
__device__ __half g_W4h[C4 * C3], g_W4l[C4 * C3];

__device__ __half g_f2h[BMAX * NPT * C2], g_f2l[BMAX * NPT * C2];
__device__ __half g_fgh[BMAX * C2], g_fgl[BMAX * C2];
__device__ float g_h[BMAX * C3];

__device__ __half g_f3h[BMAX * NPT * C3], g_f3l[BMAX * NPT * C3];
__device__ float g_p3s[BMAX * C3];
__device__ float g_p3q[BMAX * C3];
__device__ float g_bn3a[C3], g_bn3c[C3];

__device__ float g_feat[BMAX * NPT * C4];
__device__ float g_fg2[BMAX * C4];

__device__ float g_mdx[BMAX * C4];
__device__ double g_p7[BMAX * 2];
__device__ float g_inv[1];

__device__ float g_y[BMAX * C4];
__device__ float g_bnFa[C4], g_bnFc[C4];

// ================= helpers =================
__device__ __forceinline__ uint32_t smem_u32(const void* p) {
    uint32_t a;
    asm("{ .reg .u64 t; cvta.to.shared.u64 t, %1; cvt.u32.u64 %0, t; }" : "=r"(a) : "l"(p));
    return a;
}
__device__ __forceinline__ void cp_async16(uint32_t dst, const void* src) {
    asm volatile("cp.async.cg.shared.global [%0], [%1], 16;" :: "r"(dst), "l"(src));
}
#define CP_COMMIT() asm volatile("cp.async.commit_group;" ::: "memory")
#define CP_WAIT1() asm volatile("cp.async.wait_group 1;" ::: "memory")
#define CP_WAIT0() asm volatile("cp.async.wait_group 0;" ::: "memory")

__device__ __forceinline__ void ldsm4(uint32_t* r, uint32_t addr) {
    asm volatile("ldmatrix.sync.aligned.m8n8.x4.shared.b16 {%0,%1,%2,%3}, [%4];"
                 : "=r"(r[0]), "=r"(r[1]), "=r"(r[2]), "=r"(r[3]) : "r"(addr));
}
__device__ __forceinline__ void mma_f16(float* d, const uint32_t* a, uint32_t b0, uint32_t b1) {
    asm volatile(
        "mma.sync.aligned.m16n8k16.row.col.f32.f16.f16.f32 "
        "{%0,%1,%2,%3}, {%4,%5,%6,%7}, {%8,%9}, {%0,%1,%2,%3};"
        : "+f"(d[0]), "+f"(d[1]), "+f"(d[2]), "+f"(d[3])
        : "r"(a[0]), "r"(a[1]), "r"(a[2]), "r"(a[3]), "r"(b0), "r"(b1));
}
__device__ __forceinline__ void splitf(float v, __half& h, __half& l) {
    h = __float2half_rn(v);
    l = __float2half_rn(v - __half2float(h));
}

// ================= fp16 pre-split GEMM (128x64 CTA tile, occupancy 2) =================
// out[M,Nt] = (Ah+Al)[M,K] * (Bh+Bl)[Nt,K]^T + bias + gadd (3-term fp16 MMA)
// 256 threads = 8 warps (4M x 2N), warp tile 32x32 -> each M-warp = one 32-row group.
// Optional fused per-group reductions (max, sum/sqsum).
#define KC 64
// stage layout (bytes): Ahi 0 (16K), Alo 16384, Bhi 32768 (8K), Blo 40960; 128B swizzled rows
#define STAGE_B 49152
#define GEMM_SMEM (2 * STAGE_B)

#define LOAD_CHUNK(kc, stg) do {                                   \
    uint32_t _b = sb + (uint32_t)(stg) * STAGE_B;                  \
    const __half* _ah = aSrcH + (size_t)(kc) * KC;                 \
    const __half* _al = aSrcL + (size_t)(kc) * KC;                 \
    const __half* _bh = bSrcH + (size_t)(kc) * KC;                 \
    const __half* _bl = bSrcL + (size_t)(kc) * KC;                 \
    _Pragma("unroll")                                              \
    for (int _j = 0; _j < 4; _j++) {                               \
        cp_async16(_b + dswA[_j], _ah + _j * 8);                   \
        cp_async16(_b + 16384 + dswA[_j], _al + _j * 8);           \
    }                                                              \
    _Pragma("unroll")                                              \
    for (int _j = 0; _j < 2; _j++) {                               \
        cp_async16(_b + 32768 + dswB[_j], _bh + _j * 32);          \
        cp_async16(_b + 40960 + dswB[_j], _bl + _j * 32);          \
    }                                                              \
    CP_COMMIT();                                                   \
} while (0)

__global__ void __launch_bounds__(256, 2) k_gemm(
    const __half* __restrict__ Ah, const __half* __restrict__ Al, int lda,
    const __half* __restrict__ Bh, const __half* __restrict__ Bl, int ldb,
    const float* __restrict__ bias, const float* __restrict__ gadd, int ldg,
    float* __restrict__ outF, __half* __restrict__ outH, __half* __restrict__ outL,
    float* __restrict__ maxF, __half* __restrict__ maxH, __half* __restrict__ maxL,
    float* __restrict__ statS, float* __restrict__ statQ,
    int ntotal, int nchunks, int ntiles) {
    extern __shared__ char smem[];
    uint32_t sb = smem_u32(smem);
    int t = threadIdx.x, wid = t >> 5, lane = t & 31;
    int gid = lane >> 2, tig = lane & 3;
    int mt = blockIdx.x / ntiles, nt = blockIdx.x % ntiles;
    int m0 = mt * 128, n0 = nt * 64;
    int warpM = (wid & 3) * 32, warpN = (wid >> 2) * 32;

    // A loader: thread t covers row t>>1, half (t&1) -> 4x16B per array
    int lrow = t >> 1;
    int lc = (t & 1) * 4;
    uint32_t dswA[4];
#pragma unroll
    for (int j = 0; j < 4; j++)
        dswA[j] = (uint32_t)lrow * 128 + (((uint32_t)(lc + j) * 16) ^ ((uint32_t)(lrow & 7) << 4));
    // B loader: thread t covers row t>>2, chunks {t&3, (t&3)+4}
    int brow = t >> 2, bj = t & 3;
    uint32_t dswB[2];
#pragma unroll
    for (int j = 0; j < 2; j++) {
        int cidx = bj + j * 4;
        dswB[j] = (uint32_t)brow * 128 + (((uint32_t)cidx * 16) ^ ((uint32_t)(brow & 7) << 4));
    }
    const __half* aSrcH = Ah + (size_t)(m0 + lrow) * lda + lc * 8;
    const __half* aSrcL = Al + (size_t)(m0 + lrow) * lda + lc * 8;
    const __half* bSrcH = Bh + (size_t)(n0 + brow) * ldb + bj * 8;
    const __half* bSrcL = Bl + (size_t)(n0 + brow) * ldb + bj * 8;

    // fragment addressing (byte-logical offset swizzle)
    uint32_t xorv = (uint32_t)(lane & 7) << 4;
    uint32_t aOff0 = (uint32_t)(warpM + (lane & 15)) * 128;
    uint32_t aOff1 = aOff0 + 16 * 128;
    uint32_t kselA = (uint32_t)(lane & 16);
    uint32_t kselB = (uint32_t)((lane & 8) << 1);
    uint32_t bOff[2];
#pragma unroll
    for (int np = 0; np < 2; np++)
        bOff[np] = (uint32_t)(warpN + np * 16 + (lane & 7) + ((lane & 16) >> 1)) * 128;

    LOAD_CHUNK(0, 0);

    float acc[2][4][4];
#pragma unroll
    for (int mi = 0; mi < 2; mi++)
#pragma unroll
        for (int ni = 0; ni < 4; ni++)
#pragma unroll
            for (int c = 0; c < 4; c++) acc[mi][ni][c] = 0.f;

    for (int kc = 0; kc < nchunks; kc++) {
        int p = kc & 1;
        if (kc + 1 < nchunks) {
            LOAD_CHUNK(kc + 1, p ^ 1);
            CP_WAIT1();
        } else {
            CP_WAIT0();
        }
        __syncthreads();
        uint32_t bA = sb + (uint32_t)p * STAGE_B;
#pragma unroll
        for (int ks = 0; ks < KC; ks += 16) {
            uint32_t offA = (((uint32_t)(2 * ks)) + kselA) ^ xorv;
            uint32_t offB = (((uint32_t)(2 * ks)) + kselB) ^ xorv;
            uint32_t ah0[4], ah1[4], al0[4], al1[4];
            ldsm4(ah0, bA + aOff0 + offA);
            ldsm4(ah1, bA + aOff1 + offA);
            ldsm4(al0, bA + 16384 + aOff0 + offA);
            ldsm4(al1, bA + 16384 + aOff1 + offA);
#pragma unroll
            for (int np = 0; np < 2; np++) {
                uint32_t bh[4], bl[4];
                ldsm4(bh, bA + 32768 + bOff[np] + offB);
                ldsm4(bl, bA + 40960 + bOff[np] + offB);
                mma_f16(acc[0][2 * np], ah0, bh[0], bh[1]);
                mma_f16(acc[1][2 * np], ah1, bh[0], bh[1]);
                mma_f16(acc[0][2 * np], ah0, bl[0], bl[1]);
                mma_f16(acc[1][2 * np], ah1, bl[0], bl[1]);
                mma_f16(acc[0][2 * np], al0, bh[0], bh[1]);
                mma_f16(acc[1][2 * np], al1, bh[0], bh[1]);
                mma_f16(acc[0][2 * np + 1], ah0, bh[2], bh[3]);
                mma_f16(acc[1][2 * np + 1], ah1, bh[2], bh[3]);
                mma_f16(acc[0][2 * np + 1], ah0, bl[2], bl[3]);
                mma_f16(acc[1][2 * np + 1], ah1, bl[2], bl[3]);
                mma_f16(acc[0][2 * np + 1], al0, bh[2], bh[3]);
                mma_f16(acc[1][2 * np + 1], al1, bh[2], bh[3]);
            }
        }
        __syncthreads();
    }

    // ---------- epilogue ----------
    int g = (m0 + warpM) >> 5;  // this M-warp's group (32 rows == 1 group)
    const float* grow = gadd ? (gadd + (size_t)g * ldg + n0) : nullptr;

    // main store
#pragma unroll
    for (int mi = 0; mi < 2; mi++) {
        int gm = m0 + warpM + mi * 16 + gid;
#pragma unroll
        for (int ni = 0; ni < 4; ni++) {
            int n = warpN + ni * 8 + 2 * tig;
            float add0 = 0.f, add1 = 0.f;
            if (bias) { add0 += bias[n0 + n]; add1 += bias[n0 + n + 1]; }
            if (grow) { add0 += grow[n]; add1 += grow[n + 1]; }
            float v00 = acc[mi][ni][0] + add0, v01 = acc[mi][ni][1] + add1;
            float v10 = acc[mi][ni][2] + add0, v11 = acc[mi][ni][3] + add1;
            if (outF) {
                *(float2*)(outF + (size_t)gm * ntotal + n0 + n) = make_float2(v00, v01);
                *(float2*)(outF + (size_t)(gm + 8) * ntotal + n0 + n) = make_float2(v10, v11);
            } else {
                __half h00, l00, h01, l01, h10, l10, h11, l11;
                splitf(v00, h00, l00); splitf(v01, h01, l01);
                splitf(v10, h10, l10); splitf(v11, h11, l11);
                *(__half2*)(outH + (size_t)gm * ntotal + n0 + n) = __halves2half2(h00, h01);
                *(__half2*)(outL + (size_t)gm * ntotal + n0 + n) = __halves2half2(l00, l01);
                *(__half2*)(outH + (size_t)(gm + 8) * ntotal + n0 + n) = __halves2half2(h10, h11);
                *(__half2*)(outL + (size_t)(gm + 8) * ntotal + n0 + n) = __halves2half2(l10, l11);
            }
        }
    }

    // fused per-group column max
    if (maxF || maxH) {
#pragma unroll
        for (int ni = 0; ni < 4; ni++) {
            int n = warpN + ni * 8 + 2 * tig;
            float mx0 = fmaxf(fmaxf(acc[0][ni][0], acc[0][ni][2]),
                              fmaxf(acc[1][ni][0], acc[1][ni][2]));
            float mx1 = fmaxf(fmaxf(acc[0][ni][1], acc[0][ni][3]),
                              fmaxf(acc[1][ni][1], acc[1][ni][3]));
#pragma unroll
            for (int m = 4; m <= 16; m <<= 1) {
                mx0 = fmaxf(mx0, __shfl_xor_sync(0xffffffffu, mx0, m));
                mx1 = fmaxf(mx1, __shfl_xor_sync(0xffffffffu, mx1, m));
            }
            if (gid == 0) {
                float add0 = bias ? bias[n0 + n] : 0.f;
                float add1 = bias ? bias[n0 + n + 1] : 0.f;
                float v0 = mx0 + add0, v1 = mx1 + add1;
                if (maxF) {
                    *(float2*)(maxF + (size_t)g * ntotal + n0 + n) = make_float2(v0, v1);
                } else {
                    __half h0, l0, h1, l1;
                    splitf(v0, h0, l0); splitf(v1, h1, l1);
                    *(__half2*)(maxH + (size_t)g * ntotal + n0 + n) = __halves2half2(h0, h1);
                    *(__half2*)(maxL + (size_t)g * ntotal + n0 + n) = __halves2half2(l0, l1);
                }
            }
        }
    }

    // fused per-group column sum / sqsum (for BN partials)
    if (statS) {
#pragma unroll
        for (int ni = 0; ni < 4; ni++) {
            int n = warpN + ni * 8 + 2 * tig;
            float add0 = 0.f, add1 = 0.f;
            if (bias) { add0 += bias[n0 + n]; add1 += bias[n0 + n + 1]; }
            if (grow) { add0 += grow[n]; add1 += grow[n + 1]; }
            float s0 = 0.f, q0 = 0.f, s1 = 0.f, q1 = 0.f;
#pragma unroll
            for (int mi = 0; mi < 2; mi++) {
                float v;
                v = acc[mi][ni][0] + add0; s0 += v; q0 = fmaf(v, v, q0);
                v = acc[mi][ni][2] + add0; s0 += v; q0 = fmaf(v, v, q0);
                v = acc[mi][ni][1] + add1; s1 += v; q1 = fmaf(v, v, q1);
                v = acc[mi][ni][3] + add1; s1 += v; q1 = fmaf(v, v, q1);
            }
#pragma unroll
            for (int m = 4; m <= 16; m <<= 1) {
                s0 += __shfl_xor_sync(0xffffffffu, s0, m);
                q0 += __shfl_xor_sync(0xffffffffu, q0, m);
                s1 += __shfl_xor_sync(0xffffffffu, s1, m);
                q1 += __shfl_xor_sync(0xffffffffu, q1, m);
            }
            if (gid == 0) {
                *(float2*)(statS + (size_t)g * ntotal + n0 + n) = make_float2(s0, s1);
                *(float2*)(statQ + (size_t)g * ntotal + n0 + n) = make_float2(q0, q1);
            }
        }
    }
}

// ---------------- weight split + Wf transpose (merged prep) ----------------
__global__ void k_prep(const float* __restrict__ W2, const float* __restrict__ W3,
                       const float* __restrict__ W4, const float* __restrict__ Wf) {
    int i = blockIdx.x * blockDim.x + threadIdx.x;
    const int N2 = C2 * C1, N3 = C3 * C3, N4 = C4 * C3, NF = CF * C4;
    float v; __half h, l;
    if (i < N2) {
        v = W2[i]; splitf(v, h, l); g_W2h[i] = h; g_W2l[i] = l;
    } else if (i < N2 + N3) {
        int j = i - N2; v = W3[j]; splitf(v, h, l); g_W3h[j] = h; g_W3l[j] = l;
    } else if (i < N2 + N3 + N4) {
        int j = i - N2 - N3; v = W4[j]; splitf(v, h, l); g_W4h[j] = h; g_W4l[j] = l;
    } else if (i < N2 + N3 + N4 + NF) {
        int j = i - N2 - N3 - N4;
        int c = j / C4, o = j % C4;
        g_WfT[j] = Wf[o * CF + c];
    }
}

// ---------------- conv1: (B,32,3) -> raw f1 + per-b channel partials ----------------
__global__ void __launch_bounds__(C1) k_conv1(const float* __restrict__ pg,
                                              const float* __restrict__ W1,
                                              const float* __restrict__ b1) {
    int b = blockIdx.x;
    int o = threadIdx.x;
    __shared__ float sp[NPT * 3];
    for (int i = o; i < NPT * 3; i += C1) sp[i] = pg[b * NPT * 3 + i];
    __syncthreads();
    float w0 = W1[o * 3 + 0], w1 = W1[o * 3 + 1], w2 = W1[o * 3 + 2], bb = b1[o];
    float s = 0.f, q = 0.f;
#pragma unroll
    for (int l = 0; l < NPT; l++) {
        float v = fmaf(sp[l * 3 + 0], w0, fmaf(sp[l * 3 + 1], w1, fmaf(sp[l * 3 + 2], w2, bb)));
        g_f1[(b * NPT + l) * C1 + o] = v;
        s += v;
        q = fmaf(v, v, q);
    }
    g_p1s[b * C1 + o] = s;
    g_p1q[b * C1 + o] = q;
}

// ---------------- BN-stats reduce: 8 channels/block, sector-efficient reads ----------------
#define SCH 8
__global__ void k_stats(const float* __restrict__ ps, const float* __restrict__ pq,
                        const float* __restrict__ gamma, const float* __restrict__ beta,
                        float* __restrict__ aout, float* __restrict__ cout,
                        int nb, int C, int perB) {
    int o0 = blockIdx.x * SCH;
    int t = threadIdx.x;
    int ch = t & (SCH - 1), bsub = t >> 3;   // 32 b-lanes x 8 channels
    double s = 0.0, q = 0.0;
    for (int b = bsub; b < nb; b += 32) {
        size_t idx = (size_t)b * C + o0 + ch;
        s += (double)ps[idx];
        q += (double)pq[idx];
    }
    __shared__ double sh[256], sh2[256];
    sh[t] = s; sh2[t] = q;
    __syncthreads();
    for (int st = 128; st >= SCH; st >>= 1) {
        if (t < st) { sh[t] += sh[t + st]; sh2[t] += sh2[t + st]; }
        __syncthreads();
    }
    if (t < SCH) {
        double N = (double)nb * (double)perB;
        double mean = sh[t] / N;
        double var = sh2[t] / N - mean * mean;
        int o = o0 + t;
        float a = gamma[o] * rsqrtf((float)var + EPSF);
        aout[o] = a;
        cout[o] = beta[o] - (float)mean * a;
    }
}

// ---------------- bn+relu+split: f32 in -> half pair out (8 elems/thread, 16B IO) ----------------
__global__ void k_bnsplit(const float* __restrict__ x, const float* __restrict__ a,
                          const float* __restrict__ c, __half* __restrict__ oh,
                          __half* __restrict__ ol, int cmask, int n8) {
    int i = blockIdx.x * blockDim.x + threadIdx.x;
    if (i < n8) {
        int j = 8 * i;
        int c0 = j & cmask;
        float4 v0 = *(const float4*)(x + j);
        float4 v1 = *(const float4*)(x + j + 4);
        float4 a0 = *(const float4*)(a + c0);
        float4 a1 = *(const float4*)(a + c0 + 4);
        float4 b0 = *(const float4*)(c + c0);
        float4 b1 = *(const float4*)(c + c0 + 4);
        float u[8];
        u[0] = fmaxf(fmaf(v0.x, a0.x, b0.x), 0.f);
        u[1] = fmaxf(fmaf(v0.y, a0.y, b0.y), 0.f);
        u[2] = fmaxf(fmaf(v0.z, a0.z, b0.z), 0.f);
        u[3] = fmaxf(fmaf(v0.w, a0.w, b0.w), 0.f);
        u[4] = fmaxf(fmaf(v1.x, a1.x, b1.x), 0.f);
        u[5] = fmaxf(fmaf(v1.y, a1.y, b1.y), 0.f);
        u[6] = fmaxf(fmaf(v1.z, a1.z, b1.z), 0.f);
        u[7] = fmaxf(fmaf(v1.w, a1.w, b1.w), 0.f);
        __half2 hh[4], ll[4];
#pragma unroll
        for (int k = 0; k < 4; k++) {
            __half h0, l0, h1, l1;
            splitf(u[2 * k], h0, l0);
            splitf(u[2 * k + 1], h1, l1);
            hh[k] = __halves2half2(h0, h1);
            ll[k] = __halves2half2(l0, l1);
        }
        *(uint4*)(oh + j) = *(uint4*)hh;
        *(uint4*)(ol + j) = *(uint4*)ll;
    }
}

// ---------------- bn+relu+split in place on a half pair (8 elems/thread, 16B IO) ----------------
__global__ void k_bnsplit2(__half* __restrict__ xh, __half* __restrict__ xl,
                           const float* __restrict__ a, const float* __restrict__ c,
                           int cmask, int n8) {
    int i = blockIdx.x * blockDim.x + threadIdx.x;
    if (i < n8) {
        int j = 8 * i;
        int c0 = j & cmask;
        uint4 rh = *(uint4*)(xh + j);
        uint4 rl = *(uint4*)(xl + j);
        const __half2* ph = (const __half2*)&rh;
        const __half2* pl = (const __half2*)&rl;
        float4 a0 = *(const float4*)(a + c0);
        float4 a1 = *(const float4*)(a + c0 + 4);
        float4 b0 = *(const float4*)(c + c0);
        float4 b1 = *(const float4*)(c + c0 + 4);
        float aa[8] = {a0.x, a0.y, a0.z, a0.w, a1.x, a1.y, a1.z, a1.w};
        float bb[8] = {b0.x, b0.y, b0.z, b0.w, b1.x, b1.y, b1.z, b1.w};
        __half2 hh[4], ll[4];
#pragma unroll
        for (int k = 0; k < 4; k++) {
            float2 vh = __half22float2(ph[k]);
            float2 vl = __half22float2(pl[k]);
            float u0 = fmaxf(fmaf(vh.x + vl.x, aa[2 * k], bb[2 * k]), 0.f);
            float u1 = fmaxf(fmaf(vh.y + vl.y, aa[2 * k + 1], bb[2 * k + 1]), 0.f);
            __half h0, l0, h1, l1;
            splitf(u0, h0, l0);
            splitf(u1, h1, l1);
            hh[k] = __halves2half2(h0, h1);
            ll[k] = __halves2half2(l0, l1);
        }
        *(uint4*)(xh + j) = *(uint4*)hh;
        *(uint4*)(xl + j) = *(uint4*)ll;
    }
}

// ---------------- knn + dx statistics per group ----------------
__global__ void __launch_bounds__(C4) k_knn(const float* __restrict__ pgin) {
    extern __shared__ float sm[];
    float* ft = sm;                         // 32*384
    float* sp = ft + NPT * C4;              // 96
    float* sq = sp + NPT * 3;               // 32
    float* d = sq + NPT;                    // 1024
    int* sidx = (int*)(d + NPT * NPT);      // 256
    int b = blockIdx.x, t = threadIdx.x;
    for (int i = t; i < NPT * C4; i += C4) ft[i] = g_feat[(size_t)b * NPT * C4 + i];
    for (int i = t; i < NPT * 3; i += C4) sp[i] = pgin[b * NPT * 3 + i];
    __syncthreads();
    if (t < NPT) {
        float x = sp[t * 3], y = sp[t * 3 + 1], z = sp[t * 3 + 2];
        sq[t] = x * x + y * y + z * z;
    }
    __syncthreads();
    for (int i = t; i < NPT * NPT; i += C4) {
        int n = i / NPT, m = i % NPT;
        float dot = sp[n * 3] * sp[m * 3] + sp[n * 3 + 1] * sp[m * 3 + 1] + sp[n * 3 + 2] * sp[m * 3 + 2];
        d[i] = sq[n] + sq[m] - 2.f * dot;
    }
    __syncthreads();
    if (t < NPT) {
        unsigned chosen = 0;
        for (int k = 0; k < KG; k++) {
            float best = CUDART_INF_F;
            int bi = 0;
            for (int m = 0; m < NPT; m++) {
                if ((chosen >> m) & 1u) continue;
                float dv = d[t * NPT + m];
                if (dv < best) { best = dv; bi = m; }
            }
            chosen |= 1u << bi;
            sidx[t * KG + k] = bi;
        }
    }
    __syncthreads();
    int c = t;
    float chsum = 0.f, gq = 0.f;
    for (int n = 0; n < NPT; n++) {
        float fn = ft[n * C4 + c];
#pragma unroll
        for (int k = 0; k < KG; k++) {
            int j = sidx[n * KG + k];
            float dx = ft[j * C4 + c] - fn;
            chsum += dx;
            gq = fmaf(dx, dx, gq);
        }
    }
    g_mdx[b * C4 + c] = chsum * (1.f / (float)(NPT * KG));
    __syncthreads();
    float* r1 = d;
    float* r2 = d + 512;
    r1[t] = chsum; r2[t] = gq;
    __syncthreads();
    if (t < 128) {
        r1[t] += r1[t + 128] + r1[t + 256];
        r2[t] += r2[t + 128] + r2[t + 256];
    }
    __syncthreads();
    for (int st = 64; st > 0; st >>= 1) {
        if (t < st) { r1[t] += r1[t + st]; r2[t] += r2[t + st]; }
        __syncthreads();
    }
    if (t == 0) {
        g_p7[2 * b + 0] = (double)r1[0];
        g_p7[2 * b + 1] = (double)r2[0];
    }
}

// ---------------- global std (ddof=1) ----------------
__global__ void k_std(int nb) {
    int t = threadIdx.x;
    double s = 0.0, q = 0.0;
    for (int b = t; b < nb; b += 256) {
        s += g_p7[2 * b + 0];
        q += g_p7[2 * b + 1];
    }
    __shared__ double sh[256], sh2[256];
    sh[t] = s; sh2[t] = q;
    __syncthreads();
    for (int st = 128; st > 0; st >>= 1) {
        if (t < st) { sh[t] += sh[t + st]; sh2[t] += sh2[t + st]; }
        __syncthreads();
    }
    if (t == 0) {
        double N = (double)nb * NPT * KG * C4;
        double var = (sh2[0] - sh[0] * sh[0] / N) / (N - 1.0);
        float sd = sqrtf((float)var);
        g_inv[0] = 1.f / (sd + EPSF);
    }
}

// ---------------- fused layer GEMV (768 -> 384) ----------------
__global__ void __launch_bounds__(C4) k_fuse(const float* __restrict__ alpha,
                                             const float* __restrict__ beta_aff,
                                             const float* __restrict__ bf) {
    __shared__ float sin_[CF];
    int b = blockIdx.x, t = threadIdx.x;
    float inv = g_inv[0];
    sin_[t] = g_fg2[b * C4 + t];
    sin_[C4 + t] = fmaf(alpha[t] * inv, g_mdx[b * C4 + t], beta_aff[t]);
    __syncthreads();
    int o = t;
    float acc = bf[o];
    const float4* s4 = (const float4*)sin_;
    for (int c0 = 0; c0 < CF; c0 += 4) {
        float4 sv = s4[c0 >> 2];
        acc = fmaf(sv.x, g_WfT[(c0 + 0) * C4 + o], acc);
        acc = fmaf(sv.y, g_WfT[(c0 + 1) * C4 + o], acc);
        acc = fmaf(sv.z, g_WfT[(c0 + 2) * C4 + o], acc);
        acc = fmaf(sv.w, g_WfT[(c0 + 3) * C4 + o], acc);
    }
    g_y[b * C4 + o] = acc;
}

// ---------------- final BN stats over y: 8 channels/block, sector-efficient ----------------
__global__ void k_statsF(const float* __restrict__ gamma, const float* __restrict__ beta, int nb) {
    int o0 = blockIdx.x * SCH;
    int t = threadIdx.x;
    int ch = t & (SCH - 1), bsub = t >> 3;
    double s = 0.0, q = 0.0;
    for (int b = bsub; b < nb; b += 32) {
        double v = (double)g_y[(size_t)b * C4 + o0 + ch];
        s += v; q += v * v;
    }
    __shared__ double sh[256], sh2[256];
    sh[t] = s; sh2[t] = q;
    __syncthreads();
    for (int st = 128; st >= SCH; st >>= 1) {
        if (t < st) { sh[t] += sh[t + st]; sh2[t] += sh2[t + st]; }
        __syncthreads();
    }
    if (t < SCH) {
        double N = (double)nb;
        double mean = sh[t] / N;
        double var = sh2[t] / N - mean * mean;
        int o = o0 + t;
        float a = gamma[o] * rsqrtf((float)var + EPSF);
        g_bnFa[o] = a;
        g_bnFc[o] = beta[o] - (float)mean * a;
    }
}

// ---------------- final apply (4 elems/thread) ----------------
__global__ void k_out(float* __restrict__ out, int n4) {
    int i = blockIdx.x * blockDim.x + threadIdx.x;
    if (i < n4) {
        int j = 4 * i;
        int o = j % C4;
        float4 v = *(const float4*)(g_y + j);
        float4 r;
        r.x = fmaxf(fmaf(v.x, g_bnFa[o], g_bnFc[o]), 0.f);
        r.y = fmaxf(fmaf(v.y, g_bnFa[o + 1], g_bnFc[o + 1]), 0.f);
        r.z = fmaxf(fmaf(v.z, g_bnFa[o + 2], g_bnFc[o + 2]), 0.f);
        r.w = fmaxf(fmaf(v.w, g_bnFa[o + 3], g_bnFc[o + 3]), 0.f);
        *(float4*)(out + j) = r;
    }
}

// ---------------- launch ----------------
extern "C" void kernel_launch(void* const* d_in, const int* in_sizes, int n_in,
                              void* d_out, int out_size) {
    const float* pg      = (const float*)d_in[0];
    const float* W1      = (const float*)d_in[1];
    const float* b1      = (const float*)d_in[2];
    const float* gamma1  = (const float*)d_in[3];
    const float* beta1   = (const float*)d_in[4];
    const float* W2      = (const float*)d_in[5];
    const float* b2      = (const float*)d_in[6];
    const float* W3      = (const float*)d_in[7];
    const float* b3      = (const float*)d_in[8];
    const float* gamma3  = (const float*)d_in[9];
    const float* beta3   = (const float*)d_in[10];
    const float* W4      = (const float*)d_in[11];
    const float* b4      = (const float*)d_in[12];
    const float* alpha   = (const float*)d_in[13];
    const float* beta_af = (const float*)d_in[14];
    const float* Wf      = (const float*)d_in[15];
    const float* bf      = (const float*)d_in[16];
    const float* gammaf  = (const float*)d_in[17];
    const float* betaf   = (const float*)d_in[18];

    int nb = in_sizes[0] / (NPT * 3);   // 1024
    int M = nb * NPT;                   // 32768
    int mtiles = M / 128;               // 256

    int knn_smem = (NPT * C4 + NPT * 3 + NPT + NPT * NPT) * 4 + NPT * KG * 4;
    cudaFuncSetAttribute(k_knn, cudaFuncAttributeMaxDynamicSharedMemorySize, knn_smem);
    cudaFuncSetAttribute(k_gemm, cudaFuncAttributeMaxDynamicSharedMemorySize, GEMM_SMEM);

    float *f1, *feat, *h;
    cudaGetSymbolAddress((void**)&f1, g_f1);
    cudaGetSymbolAddress((void**)&feat, g_feat);
    cudaGetSymbolAddress((void**)&h, g_h);
    __half *f1h, *f1l, *W2h, *W2l, *W3h, *W3l, *W4h, *W4l, *f2h, *f2l, *fgh, *fgl, *f3h, *f3l;
    cudaGetSymbolAddress((void**)&f1h, g_f1h);
    cudaGetSymbolAddress((void**)&f1l, g_f1l);
    cudaGetSymbolAddress((void**)&W2h, g_W2h);
    cudaGetSymbolAddress((void**)&W2l, g_W2l);
    cudaGetSymbolAddress((void**)&W3h, g_W3h);
    cudaGetSymbolAddress((void**)&W3l, g_W3l);
    cudaGetSymbolAddress((void**)&W4h, g_W4h);
    cudaGetSymbolAddress((void**)&W4l, g_W4l);
    cudaGetSymbolAddress((void**)&f2h, g_f2h);
    cudaGetSymbolAddress((void**)&f2l, g_f2l);
    cudaGetSymbolAddress((void**)&fgh, g_fgh);
    cudaGetSymbolAddress((void**)&fgl, g_fgl);
    cudaGetSymbolAddress((void**)&f3h, g_f3h);
    cudaGetSymbolAddress((void**)&f3l, g_f3l);
    float *p1s, *p1q, *bn1a, *bn1c, *p3s, *p3q, *bn3a, *bn3c, *fg2;
    cudaGetSymbolAddress((void**)&p1s, g_p1s);
    cudaGetSymbolAddress((void**)&p1q, g_p1q);
    cudaGetSymbolAddress((void**)&bn1a, g_bn1a);
    cudaGetSymbolAddress((void**)&bn1c, g_bn1c);
    cudaGetSymbolAddress((void**)&p3s, g_p3s);
    cudaGetSymbolAddress((void**)&p3q, g_p3q);
    cudaGetSymbolAddress((void**)&bn3a, g_bn3a);
    cudaGetSymbolAddress((void**)&bn3c, g_bn3c);
    cudaGetSymbolAddress((void**)&fg2, g_fg2);

    const int NPREP = C2 * C1 + C3 * C3 + C4 * C3 + CF * C4;
    k_prep<<<(NPREP + 255) / 256, 256>>>(W2, W3, W4, Wf);
    k_conv1<<<nb, C1>>>(pg, W1, b1);
    k_stats<<<C1 / SCH, 256>>>(p1s, p1q, gamma1, beta1, bn1a, bn1c, nb, C1, NPT);
    k_bnsplit<<<(M * C1 / 8 + 255) / 256, 256>>>(f1, bn1a, bn1c, f1h, f1l, C1 - 1, M * C1 / 8);

    // conv2: f2[M,256] = f1bn[M,128] x W2^T + b2  -> split output + fused fg max
    k_gemm<<<mtiles * (C2 / 64), 256, GEMM_SMEM>>>(f1h, f1l, C1, W2h, W2l, C1, b2, nullptr, 0,
                                                   nullptr, f2h, f2l, nullptr, fgh, fgl,
                                                   nullptr, nullptr, C2, C1 / KC, C2 / 64);

    // h[nb,512] = fg[nb,256] x W3[:,0:256]^T + b3  -> f32
    k_gemm<<<(nb / 128) * (C3 / 64), 256, GEMM_SMEM>>>(fgh, fgl, C2, W3h, W3l, C3, b3, nullptr, 0,
                                                       h, nullptr, nullptr, nullptr, nullptr,
                                                       nullptr, nullptr, nullptr, C3, C2 / KC, C3 / 64);

    // conv3: f3[M,512] = f2[M,256] x W3[:,256:512]^T + h[group] -> split output + fused BN partials
    k_gemm<<<mtiles * (C3 / 64), 256, GEMM_SMEM>>>(f2h, f2l, C2, W3h + C2, W3l + C2, C3, nullptr, h, C3,
                                                   nullptr, f3h, f3l, nullptr, nullptr, nullptr,
                                                   p3s, p3q, C3, C2 / KC, C3 / 64);

    k_stats<<<C3 / SCH, 256>>>(p3s, p3q, gamma3, beta3, bn3a, bn3c, nb, C3, NPT);
    k_bnsplit2<<<(M * C3 / 8 + 255) / 256, 256>>>(f3h, f3l, bn3a, bn3c, C3 - 1, M * C3 / 8);

    // conv4: feat[M,384] = f3bn[M,512] x W4^T + b4  -> f32 + fused fg2 max
    k_gemm<<<mtiles * (C4 / 64), 256, GEMM_SMEM>>>(f3h, f3l, C3, W4h, W4l, C3, b4, nullptr, 0,
                                                   feat, nullptr, nullptr, fg2, nullptr, nullptr,
                                                   nullptr, nullptr, C4, C3 / KC, C4 / 64);

    k_knn<<<nb, C4, knn_smem>>>(pg);
    k_std<<<1, 256>>>(nb);
    k_fuse<<<nb, C4>>>(alpha, beta_af, bf);
    k_statsF<<<C4 / SCH, 256>>>(gammaf, betaf, nb);
    k_out<<<(nb * C4 / 4 + 255) / 256, 256>>>((float*)d_out, nb * C4 / 4);
}

// round 12
// speedup vs baseline: 1.5122x; 1.5122x over previous
#include <cuda_runtime.h>
#include <cuda_bf16.h>
#include <cuda_fp16.h>
#include <math_constants.h>
#include <cstdint>

#define NPT 32
#define C1 128
#define C2 256
#define C3 512
#define C4 384
#define CF 768
#define KG 8
#define BMAX 1024
#define EPSF 1e-5f

// ---------------- scratch (device globals; no allocation) ----------------
__device__ float g_WfT[CF * C4];

__device__ float g_f1[BMAX * NPT * C1];
__device__ float g_p1s[BMAX * C1];
__device__ float g_p1q[BMAX * C1];
__device__ float g_bn1a[C1], g_bn1c[C1];

__device__ __half g_f1h[BMAX * NPT * C1], g_f1l[BMAX * NPT * C1];
__device__ __half g_W2h[C2 * C1], g_W2l[C2 * C1];
__device__ __half g_W3h[C3 * C3], g_W3l[C3 * C3];
__device__ __half g_W4h[C4 * C3], g_W4l[C4 * C3];

__device__ __half g_f2h[BMAX * NPT * C2], g_f2l[BMAX * NPT * C2];
__device__ __half g_fgh[BMAX * C2], g_fgl[BMAX * C2];
__device__ float g_h[BMAX * C3];

__device__ __half g_f3h[BMAX * NPT * C3], g_f3l[BMAX * NPT * C3];
__device__ float g_p3s[BMAX * C3];
__device__ float g_p3q[BMAX * C3];
__device__ float g_bn3a[C3], g_bn3c[C3];

__device__ float g_feat[BMAX * NPT * C4];
__device__ float g_fg2[BMAX * C4];

__device__ float g_mdx[BMAX * C4];
__device__ double g_p7[BMAX * 2];
__device__ float g_inv[1];

__device__ float g_y[BMAX * C4];
__device__ float g_bnFa[C4], g_bnFc[C4];

// ================= helpers =================
__device__ __forceinline__ uint32_t smem_u32(const void* p) {
    uint32_t a;
    asm("{ .reg .u64 t; cvta.to.shared.u64 t, %1; cvt.u32.u64 %0, t; }" : "=r"(a) : "l"(p));
    return a;
}
__device__ __forceinline__ void cp_async16(uint32_t dst, const void* src) {
    asm volatile("cp.async.cg.shared.global [%0], [%1], 16;" :: "r"(dst), "l"(src));
}
#define CP_COMMIT() asm volatile("cp.async.commit_group;" ::: "memory")
#define CP_WAIT1() asm volatile("cp.async.wait_group 1;" ::: "memory")
#define CP_WAIT0() asm volatile("cp.async.wait_group 0;" ::: "memory")

__device__ __forceinline__ void ldsm4(uint32_t* r, uint32_t addr) {
    asm volatile("ldmatrix.sync.aligned.m8n8.x4.shared.b16 {%0,%1,%2,%3}, [%4];"
                 : "=r"(r[0]), "=r"(r[1]), "=r"(r[2]), "=r"(r[3]) : "r"(addr));
}
__device__ __forceinline__ void mma_f16(float* d, const uint32_t* a, uint32_t b0, uint32_t b1) {
    asm volatile(
        "mma.sync.aligned.m16n8k16.row.col.f32.f16.f16.f32 "
        "{%0,%1,%2,%3}, {%4,%5,%6,%7}, {%8,%9}, {%0,%1,%2,%3};"
        : "+f"(d[0]), "+f"(d[1]), "+f"(d[2]), "+f"(d[3])
        : "r"(a[0]), "r"(a[1]), "r"(a[2]), "r"(a[3]), "r"(b0), "r"(b1));
}
__device__ __forceinline__ void splitf(float v, __half& h, __half& l) {
    h = __float2half_rn(v);
    l = __float2half_rn(v - __half2float(h));
}

// ================= fp16 pre-split GEMM (128x64 CTA tile, occupancy 2) =================
// out[M,Nt] = (Ah+Al)[M,K] * (Bh+Bl)[Nt,K]^T + bias + gadd (3-term fp16 MMA)
// 256 threads = 8 warps (4M x 2N), warp tile 32x32 -> each M-warp = one 32-row group.
// Optional fused per-group reductions (max, sum/sqsum).
#define KC 64
// stage layout (bytes): Ahi 0 (16K), Alo 16384, Bhi 32768 (8K), Blo 40960; 128B swizzled rows
#define STAGE_B 49152
#define GEMM_SMEM (2 * STAGE_B)

#define LOAD_CHUNK(kc, stg) do {                                   \
    uint32_t _b = sb + (uint32_t)(stg) * STAGE_B;                  \
    const __half* _ah = aSrcH + (size_t)(kc) * KC;                 \
    const __half* _al = aSrcL + (size_t)(kc) * KC;                 \
    const __half* _bh = bSrcH + (size_t)(kc) * KC;                 \
    const __half* _bl = bSrcL + (size_t)(kc) * KC;                 \
    _Pragma("unroll")                                              \
    for (int _j = 0; _j < 4; _j++) {                               \
        cp_async16(_b + dswA[_j], _ah + _j * 8);                   \
        cp_async16(_b + 16384 + dswA[_j], _al + _j * 8);           \
    }                                                              \
    _Pragma("unroll")                                              \
    for (int _j = 0; _j < 2; _j++) {                               \
        cp_async16(_b + 32768 + dswB[_j], _bh + _j * 32);          \
        cp_async16(_b + 40960 + dswB[_j], _bl + _j * 32);          \
    }                                                              \
    CP_COMMIT();                                                   \
} while (0)

__global__ void __launch_bounds__(256, 2) k_gemm(
    const __half* __restrict__ Ah, const __half* __restrict__ Al, int lda,
    const __half* __restrict__ Bh, const __half* __restrict__ Bl, int ldb,
    const float* __restrict__ bias, const float* __restrict__ gadd, int ldg,
    float* __restrict__ outF, __half* __restrict__ outH, __half* __restrict__ outL,
    float* __restrict__ maxF, __half* __restrict__ maxH, __half* __restrict__ maxL,
    float* __restrict__ statS, float* __restrict__ statQ,
    int ntotal, int nchunks, int ntiles) {
    extern __shared__ char smem[];
    uint32_t sb = smem_u32(smem);
    int t = threadIdx.x, wid = t >> 5, lane = t & 31;
    int gid = lane >> 2, tig = lane & 3;
    int mt = blockIdx.x / ntiles, nt = blockIdx.x % ntiles;
    int m0 = mt * 128, n0 = nt * 64;
    int warpM = (wid & 3) * 32, warpN = (wid >> 2) * 32;

    // A loader: thread t covers row t>>1, half (t&1) -> 4x16B per array
    int lrow = t >> 1;
    int lc = (t & 1) * 4;
    uint32_t dswA[4];
#pragma unroll
    for (int j = 0; j < 4; j++)
        dswA[j] = (uint32_t)lrow * 128 + (((uint32_t)(lc + j) * 16) ^ ((uint32_t)(lrow & 7) << 4));
    // B loader: thread t covers row t>>2, chunks {t&3, (t&3)+4}
    int brow = t >> 2, bj = t & 3;
    uint32_t dswB[2];
#pragma unroll
    for (int j = 0; j < 2; j++) {
        int cidx = bj + j * 4;
        dswB[j] = (uint32_t)brow * 128 + (((uint32_t)cidx * 16) ^ ((uint32_t)(brow & 7) << 4));
    }
    const __half* aSrcH = Ah + (size_t)(m0 + lrow) * lda + lc * 8;
    const __half* aSrcL = Al + (size_t)(m0 + lrow) * lda + lc * 8;
    const __half* bSrcH = Bh + (size_t)(n0 + brow) * ldb + bj * 8;
    const __half* bSrcL = Bl + (size_t)(n0 + brow) * ldb + bj * 8;

    // fragment addressing (byte-logical offset swizzle)
    uint32_t xorv = (uint32_t)(lane & 7) << 4;
    uint32_t aOff0 = (uint32_t)(warpM + (lane & 15)) * 128;
    uint32_t aOff1 = aOff0 + 16 * 128;
    uint32_t kselA = (uint32_t)(lane & 16);
    uint32_t kselB = (uint32_t)((lane & 8) << 1);
    uint32_t bOff[2];
#pragma unroll
    for (int np = 0; np < 2; np++)
        bOff[np] = (uint32_t)(warpN + np * 16 + (lane & 7) + ((lane & 16) >> 1)) * 128;

    LOAD_CHUNK(0, 0);

    float acc[2][4][4];
#pragma unroll
    for (int mi = 0; mi < 2; mi++)
#pragma unroll
        for (int ni = 0; ni < 4; ni++)
#pragma unroll
            for (int c = 0; c < 4; c++) acc[mi][ni][c] = 0.f;

    for (int kc = 0; kc < nchunks; kc++) {
        int p = kc & 1;
        if (kc + 1 < nchunks) {
            LOAD_CHUNK(kc + 1, p ^ 1);
            CP_WAIT1();
        } else {
            CP_WAIT0();
        }
        __syncthreads();
        uint32_t bA = sb + (uint32_t)p * STAGE_B;
#pragma unroll
        for (int ks = 0; ks < KC; ks += 16) {
            uint32_t offA = (((uint32_t)(2 * ks)) + kselA) ^ xorv;
            uint32_t offB = (((uint32_t)(2 * ks)) + kselB) ^ xorv;
            uint32_t ah0[4], ah1[4], al0[4], al1[4];
            ldsm4(ah0, bA + aOff0 + offA);
            ldsm4(ah1, bA + aOff1 + offA);
            ldsm4(al0, bA + 16384 + aOff0 + offA);
            ldsm4(al1, bA + 16384 + aOff1 + offA);
#pragma unroll
            for (int np = 0; np < 2; np++) {
                uint32_t bh[4], bl[4];
                ldsm4(bh, bA + 32768 + bOff[np] + offB);
                ldsm4(bl, bA + 40960 + bOff[np] + offB);
                mma_f16(acc[0][2 * np], ah0, bh[0], bh[1]);
                mma_f16(acc[1][2 * np], ah1, bh[0], bh[1]);
                mma_f16(acc[0][2 * np], ah0, bl[0], bl[1]);
                mma_f16(acc[1][2 * np], ah1, bl[0], bl[1]);
                mma_f16(acc[0][2 * np], al0, bh[0], bh[1]);
                mma_f16(acc[1][2 * np], al1, bh[0], bh[1]);
                mma_f16(acc[0][2 * np + 1], ah0, bh[2], bh[3]);
                mma_f16(acc[1][2 * np + 1], ah1, bh[2], bh[3]);
                mma_f16(acc[0][2 * np + 1], ah0, bl[2], bl[3]);
                mma_f16(acc[1][2 * np + 1], ah1, bl[2], bl[3]);
                mma_f16(acc[0][2 * np + 1], al0, bh[2], bh[3]);
                mma_f16(acc[1][2 * np + 1], al1, bh[2], bh[3]);
            }
        }
        __syncthreads();
    }

    // ---------- epilogue ----------
    int g = (m0 + warpM) >> 5;  // this M-warp's group (32 rows == 1 group)
    const float* grow = gadd ? (gadd + (size_t)g * ldg + n0) : nullptr;

    // main store
#pragma unroll
    for (int mi = 0; mi < 2; mi++) {
        int gm = m0 + warpM + mi * 16 + gid;
#pragma unroll
        for (int ni = 0; ni < 4; ni++) {
            int n = warpN + ni * 8 + 2 * tig;
            float add0 = 0.f, add1 = 0.f;
            if (bias) { add0 += bias[n0 + n]; add1 += bias[n0 + n + 1]; }
            if (grow) { add0 += grow[n]; add1 += grow[n + 1]; }
            float v00 = acc[mi][ni][0] + add0, v01 = acc[mi][ni][1] + add1;
            float v10 = acc[mi][ni][2] + add0, v11 = acc[mi][ni][3] + add1;
            if (outF) {
                *(float2*)(outF + (size_t)gm * ntotal + n0 + n) = make_float2(v00, v01);
                *(float2*)(outF + (size_t)(gm + 8) * ntotal + n0 + n) = make_float2(v10, v11);
            } else {
                __half h00, l00, h01, l01, h10, l10, h11, l11;
                splitf(v00, h00, l00); splitf(v01, h01, l01);
                splitf(v10, h10, l10); splitf(v11, h11, l11);
                *(__half2*)(outH + (size_t)gm * ntotal + n0 + n) = __halves2half2(h00, h01);
                *(__half2*)(outL + (size_t)gm * ntotal + n0 + n) = __halves2half2(l00, l01);
                *(__half2*)(outH + (size_t)(gm + 8) * ntotal + n0 + n) = __halves2half2(h10, h11);
                *(__half2*)(outL + (size_t)(gm + 8) * ntotal + n0 + n) = __halves2half2(l10, l11);
            }
        }
    }

    // fused per-group column max
    if (maxF || maxH) {
#pragma unroll
        for (int ni = 0; ni < 4; ni++) {
            int n = warpN + ni * 8 + 2 * tig;
            float mx0 = fmaxf(fmaxf(acc[0][ni][0], acc[0][ni][2]),
                              fmaxf(acc[1][ni][0], acc[1][ni][2]));
            float mx1 = fmaxf(fmaxf(acc[0][ni][1], acc[0][ni][3]),
                              fmaxf(acc[1][ni][1], acc[1][ni][3]));
#pragma unroll
            for (int m = 4; m <= 16; m <<= 1) {
                mx0 = fmaxf(mx0, __shfl_xor_sync(0xffffffffu, mx0, m));
                mx1 = fmaxf(mx1, __shfl_xor_sync(0xffffffffu, mx1, m));
            }
            if (gid == 0) {
                float add0 = bias ? bias[n0 + n] : 0.f;
                float add1 = bias ? bias[n0 + n + 1] : 0.f;
                float v0 = mx0 + add0, v1 = mx1 + add1;
                if (maxF) {
                    *(float2*)(maxF + (size_t)g * ntotal + n0 + n) = make_float2(v0, v1);
                } else {
                    __half h0, l0, h1, l1;
                    splitf(v0, h0, l0); splitf(v1, h1, l1);
                    *(__half2*)(maxH + (size_t)g * ntotal + n0 + n) = __halves2half2(h0, h1);
                    *(__half2*)(maxL + (size_t)g * ntotal + n0 + n) = __halves2half2(l0, l1);
                }
            }
        }
    }

    // fused per-group column sum / sqsum (for BN partials)
    if (statS) {
#pragma unroll
        for (int ni = 0; ni < 4; ni++) {
            int n = warpN + ni * 8 + 2 * tig;
            float add0 = 0.f, add1 = 0.f;
            if (bias) { add0 += bias[n0 + n]; add1 += bias[n0 + n + 1]; }
            if (grow) { add0 += grow[n]; add1 += grow[n + 1]; }
            float s0 = 0.f, q0 = 0.f, s1 = 0.f, q1 = 0.f;
#pragma unroll
            for (int mi = 0; mi < 2; mi++) {
                float v;
                v = acc[mi][ni][0] + add0; s0 += v; q0 = fmaf(v, v, q0);
                v = acc[mi][ni][2] + add0; s0 += v; q0 = fmaf(v, v, q0);
                v = acc[mi][ni][1] + add1; s1 += v; q1 = fmaf(v, v, q1);
                v = acc[mi][ni][3] + add1; s1 += v; q1 = fmaf(v, v, q1);
            }
#pragma unroll
            for (int m = 4; m <= 16; m <<= 1) {
                s0 += __shfl_xor_sync(0xffffffffu, s0, m);
                q0 += __shfl_xor_sync(0xffffffffu, q0, m);
                s1 += __shfl_xor_sync(0xffffffffu, s1, m);
                q1 += __shfl_xor_sync(0xffffffffu, q1, m);
            }
            if (gid == 0) {
                *(float2*)(statS + (size_t)g * ntotal + n0 + n) = make_float2(s0, s1);
                *(float2*)(statQ + (size_t)g * ntotal + n0 + n) = make_float2(q0, q1);
            }
        }
    }
}

// ---------------- weight split ----------------
__global__ void k_splitW(const float* __restrict__ W2, const float* __restrict__ W3,
                         const float* __restrict__ W4) {
    int i = blockIdx.x * blockDim.x + threadIdx.x;
    const int N2 = C2 * C1, N3 = C3 * C3, N4 = C4 * C3;
    float v; __half h, l;
    if (i < N2) {
        v = W2[i]; splitf(v, h, l); g_W2h[i] = h; g_W2l[i] = l;
    } else if (i < N2 + N3) {
        int j = i - N2; v = W3[j]; splitf(v, h, l); g_W3h[j] = h; g_W3l[j] = l;
    } else if (i < N2 + N3 + N4) {
        int j = i - N2 - N3; v = W4[j]; splitf(v, h, l); g_W4h[j] = h; g_W4l[j] = l;
    }
}

// ---------------- Wf transpose (for k_fuse coalescing) ----------------
__global__ void k_transposeWf(const float* __restrict__ Wf) {
    int i = blockIdx.x * blockDim.x + threadIdx.x;
    if (i < CF * C4) {
        int c = i / C4, o = i % C4;
        g_WfT[i] = Wf[o * CF + c];
    }
}

// ---------------- conv1: (B,32,3) -> raw f1 + per-b channel partials ----------------
__global__ void __launch_bounds__(C1) k_conv1(const float* __restrict__ pg,
                                              const float* __restrict__ W1,
                                              const float* __restrict__ b1) {
    int b = blockIdx.x;
    int o = threadIdx.x;
    __shared__ float sp[NPT * 3];
    for (int i = o; i < NPT * 3; i += C1) sp[i] = pg[b * NPT * 3 + i];
    __syncthreads();
    float w0 = W1[o * 3 + 0], w1 = W1[o * 3 + 1], w2 = W1[o * 3 + 2], bb = b1[o];
    float s = 0.f, q = 0.f;
#pragma unroll
    for (int l = 0; l < NPT; l++) {
        float v = fmaf(sp[l * 3 + 0], w0, fmaf(sp[l * 3 + 1], w1, fmaf(sp[l * 3 + 2], w2, bb)));
        g_f1[(b * NPT + l) * C1 + o] = v;
        s += v;
        q = fmaf(v, v, q);
    }
    g_p1s[b * C1 + o] = s;
    g_p1q[b * C1 + o] = q;
}

// ---------------- BN-stats reduce ----------------
__global__ void k_stats(const float* __restrict__ ps, const float* __restrict__ pq,
                        const float* __restrict__ gamma, const float* __restrict__ beta,
                        float* __restrict__ aout, float* __restrict__ cout,
                        int nb, int C, int perB) {
    int o = blockIdx.x;
    int t = threadIdx.x;
    double s = 0.0, q = 0.0;
    for (int b = t; b < nb; b += 256) {
        s += (double)ps[b * C + o];
        q += (double)pq[b * C + o];
    }
    __shared__ double sh[256], sh2[256];
    sh[t] = s; sh2[t] = q;
    __syncthreads();
    for (int st = 128; st > 0; st >>= 1) {
        if (t < st) { sh[t] += sh[t + st]; sh2[t] += sh2[t + st]; }
        __syncthreads();
    }
    if (t == 0) {
        double N = (double)nb * (double)perB;
        double mean = sh[0] / N;
        double var = sh2[0] / N - mean * mean;
        float a = gamma[o] * rsqrtf((float)var + EPSF);
        aout[o] = a;
        cout[o] = beta[o] - (float)mean * a;
    }
}

// ---------------- bn+relu+split: f32 in -> half pair out (2 elems/thread) ----------------
__global__ void k_bnsplit(const float* __restrict__ x, const float* __restrict__ a,
                          const float* __restrict__ c, __half* __restrict__ oh,
                          __half* __restrict__ ol, int cmask, int n2) {
    int i = blockIdx.x * blockDim.x + threadIdx.x;
    if (i < n2) {
        int j = 2 * i;
        int c0 = j & cmask, c1 = (j + 1) & cmask;
        float2 v = *(const float2*)(x + j);
        float u0 = fmaxf(fmaf(v.x, a[c0], c[c0]), 0.f);
        float u1 = fmaxf(fmaf(v.y, a[c1], c[c1]), 0.f);
        __half h0, l0, h1, l1;
        splitf(u0, h0, l0); splitf(u1, h1, l1);
        *(__half2*)(oh + j) = __halves2half2(h0, h1);
        *(__half2*)(ol + j) = __halves2half2(l0, l1);
    }
}

// ---------------- bn+relu+split in place on a half pair (2 elems/thread) ----------------
__global__ void k_bnsplit2(__half* __restrict__ xh, __half* __restrict__ xl,
                           const float* __restrict__ a, const float* __restrict__ c,
                           int cmask, int n2) {
    int i = blockIdx.x * blockDim.x + threadIdx.x;
    if (i < n2) {
        int j = 2 * i;
        int c0 = j & cmask, c1 = (j + 1) & cmask;
        float2 vh = __half22float2(*(__half2*)(xh + j));
        float2 vl = __half22float2(*(__half2*)(xl + j));
        float u0 = fmaxf(fmaf(vh.x + vl.x, a[c0], c[c0]), 0.f);
        float u1 = fmaxf(fmaf(vh.y + vl.y, a[c1], c[c1]), 0.f);
        __half h0, l0, h1, l1;
        splitf(u0, h0, l0); splitf(u1, h1, l1);
        *(__half2*)(xh + j) = __halves2half2(h0, h1);
        *(__half2*)(xl + j) = __halves2half2(l0, l1);
    }
}

// ---------------- knn + dx statistics per group ----------------
__global__ void __launch_bounds__(C4) k_knn(const float* __restrict__ pgin) {
    extern __shared__ float sm[];
    float* ft = sm;                         // 32*384
    float* sp = ft + NPT * C4;              // 96
    float* sq = sp + NPT * 3;               // 32
    float* d = sq + NPT;                    // 1024
    int* sidx = (int*)(d + NPT * NPT);      // 256
    int b = blockIdx.x, t = threadIdx.x;
    for (int i = t; i < NPT * C4; i += C4) ft[i] = g_feat[(size_t)b * NPT * C4 + i];
    for (int i = t; i < NPT * 3; i += C4) sp[i] = pgin[b * NPT * 3 + i];
    __syncthreads();
    if (t < NPT) {
        float x = sp[t * 3], y = sp[t * 3 + 1], z = sp[t * 3 + 2];
        sq[t] = x * x + y * y + z * z;
    }
    __syncthreads();
    for (int i = t; i < NPT * NPT; i += C4) {
        int n = i / NPT, m = i % NPT;
        float dot = sp[n * 3] * sp[m * 3] + sp[n * 3 + 1] * sp[m * 3 + 1] + sp[n * 3 + 2] * sp[m * 3 + 2];
        d[i] = sq[n] + sq[m] - 2.f * dot;
    }
    __syncthreads();
    if (t < NPT) {
        unsigned chosen = 0;
        for (int k = 0; k < KG; k++) {
            float best = CUDART_INF_F;
            int bi = 0;
            for (int m = 0; m < NPT; m++) {
                if ((chosen >> m) & 1u) continue;
                float dv = d[t * NPT + m];
                if (dv < best) { best = dv; bi = m; }
            }
            chosen |= 1u << bi;
            sidx[t * KG + k] = bi;
        }
    }
    __syncthreads();
    int c = t;
    float chsum = 0.f, gq = 0.f;
#pragma unroll 4
    for (int p = 0; p < NPT * KG; p++) {
        int n = p >> 3;
        int j = sidx[p];
        float dx = ft[j * C4 + c] - ft[n * C4 + c];
        chsum += dx;
        gq = fmaf(dx, dx, gq);
    }
    g_mdx[b * C4 + c] = chsum * (1.f / (float)(NPT * KG));
    __syncthreads();
    float* r1 = d;
    float* r2 = d + 512;
    r1[t] = chsum; r2[t] = gq;
    __syncthreads();
    if (t < 128) {
        r1[t] += r1[t + 128] + r1[t + 256];
        r2[t] += r2[t + 128] + r2[t + 256];
    }
    __syncthreads();
    for (int st = 64; st > 0; st >>= 1) {
        if (t < st) { r1[t] += r1[t + st]; r2[t] += r2[t + st]; }
        __syncthreads();
    }
    if (t == 0) {
        g_p7[2 * b + 0] = (double)r1[0];
        g_p7[2 * b + 1] = (double)r2[0];
    }
}

// ---------------- global std (ddof=1) ----------------
__global__ void k_std(int nb) {
    int t = threadIdx.x;
    double s = 0.0, q = 0.0;
    for (int b = t; b < nb; b += 256) {
        s += g_p7[2 * b + 0];
        q += g_p7[2 * b + 1];
    }
    __shared__ double sh[256], sh2[256];
    sh[t] = s; sh2[t] = q;
    __syncthreads();
    for (int st = 128; st > 0; st >>= 1) {
        if (t < st) { sh[t] += sh[t + st]; sh2[t] += sh2[t + st]; }
        __syncthreads();
    }
    if (t == 0) {
        double N = (double)nb * NPT * KG * C4;
        double var = (sh2[0] - sh[0] * sh[0] / N) / (N - 1.0);
        float sd = sqrtf((float)var);
        g_inv[0] = 1.f / (sd + EPSF);
    }
}

// ---------------- fused layer GEMV (768 -> 384) ----------------
__global__ void __launch_bounds__(C4) k_fuse(const float* __restrict__ alpha,
                                             const float* __restrict__ beta_aff,
                                             const float* __restrict__ bf) {
    __shared__ float sin_[CF];
    int b = blockIdx.x, t = threadIdx.x;
    float inv = g_inv[0];
    sin_[t] = g_fg2[b * C4 + t];
    sin_[C4 + t] = fmaf(alpha[t] * inv, g_mdx[b * C4 + t], beta_aff[t]);
    __syncthreads();
    int o = t;
    float acc = bf[o];
    const float4* s4 = (const float4*)sin_;
    for (int c0 = 0; c0 < CF; c0 += 4) {
        float4 sv = s4[c0 >> 2];
        acc = fmaf(sv.x, g_WfT[(c0 + 0) * C4 + o], acc);
        acc = fmaf(sv.y, g_WfT[(c0 + 1) * C4 + o], acc);
        acc = fmaf(sv.z, g_WfT[(c0 + 2) * C4 + o], acc);
        acc = fmaf(sv.w, g_WfT[(c0 + 3) * C4 + o], acc);
    }
    g_y[b * C4 + o] = acc;
}

// ---------------- final BN stats over y ----------------
__global__ void k_statsF(const float* __restrict__ gamma, const float* __restrict__ beta, int nb) {
    int o = blockIdx.x, t = threadIdx.x;
    double s = 0.0, q = 0.0;
    for (int b = t; b < nb; b += 256) {
        double v = (double)g_y[b * C4 + o];
        s += v; q += v * v;
    }
    __shared__ double sh[256], sh2[256];
    sh[t] = s; sh2[t] = q;
    __syncthreads();
    for (int st = 128; st > 0; st >>= 1) {
        if (t < st) { sh[t] += sh[t + st]; sh2[t] += sh2[t + st]; }
        __syncthreads();
    }
    if (t == 0) {
        double N = (double)nb;
        double mean = sh[0] / N;
        double var = sh2[0] / N - mean * mean;
        float a = gamma[o] * rsqrtf((float)var + EPSF);
        g_bnFa[o] = a;
        g_bnFc[o] = beta[o] - (float)mean * a;
    }
}

// ---------------- final apply ----------------
__global__ void k_out(float* __restrict__ out, int n) {
    int i = blockIdx.x * blockDim.x + threadIdx.x;
    if (i < n) {
        int o = i % C4;
        out[i] = fmaxf(fmaf(g_y[i], g_bnFa[o], g_bnFc[o]), 0.f);
    }
}

// ---------------- launch ----------------
extern "C" void kernel_launch(void* const* d_in, const int* in_sizes, int n_in,
                              void* d_out, int out_size) {
    const float* pg      = (const float*)d_in[0];
    const float* W1      = (const float*)d_in[1];
    const float* b1      = (const float*)d_in[2];
    const float* gamma1  = (const float*)d_in[3];
    const float* beta1   = (const float*)d_in[4];
    const float* W2      = (const float*)d_in[5];
    const float* b2      = (const float*)d_in[6];
    const float* W3      = (const float*)d_in[7];
    const float* b3      = (const float*)d_in[8];
    const float* gamma3  = (const float*)d_in[9];
    const float* beta3   = (const float*)d_in[10];
    const float* W4      = (const float*)d_in[11];
    const float* b4      = (const float*)d_in[12];
    const float* alpha   = (const float*)d_in[13];
    const float* beta_af = (const float*)d_in[14];
    const float* Wf      = (const float*)d_in[15];
    const float* bf      = (const float*)d_in[16];
    const float* gammaf  = (const float*)d_in[17];
    const float* betaf   = (const float*)d_in[18];

    int nb = in_sizes[0] / (NPT * 3);   // 1024
    int M = nb * NPT;                   // 32768
    int mtiles = M / 128;               // 256

    int knn_smem = (NPT * C4 + NPT * 3 + NPT + NPT * NPT) * 4 + NPT * KG * 4;
    cudaFuncSetAttribute(k_knn, cudaFuncAttributeMaxDynamicSharedMemorySize, knn_smem);
    cudaFuncSetAttribute(k_gemm, cudaFuncAttributeMaxDynamicSharedMemorySize, GEMM_SMEM);

    float *f1, *feat, *h;
    cudaGetSymbolAddress((void**)&f1, g_f1);
    cudaGetSymbolAddress((void**)&feat, g_feat);
    cudaGetSymbolAddress((void**)&h, g_h);
    __half *f1h, *f1l, *W2h, *W2l, *W3h, *W3l, *W4h, *W4l, *f2h, *f2l, *fgh, *fgl, *f3h, *f3l;
    cudaGetSymbolAddress((void**)&f1h, g_f1h);
    cudaGetSymbolAddress((void**)&f1l, g_f1l);
    cudaGetSymbolAddress((void**)&W2h, g_W2h);
    cudaGetSymbolAddress((void**)&W2l, g_W2l);
    cudaGetSymbolAddress((void**)&W3h, g_W3h);
    cudaGetSymbolAddress((void**)&W3l, g_W3l);
    cudaGetSymbolAddress((void**)&W4h, g_W4h);
    cudaGetSymbolAddress((void**)&W4l, g_W4l);
    cudaGetSymbolAddress((void**)&f2h, g_f2h);
    cudaGetSymbolAddress((void**)&f2l, g_f2l);
    cudaGetSymbolAddress((void**)&fgh, g_fgh);
    cudaGetSymbolAddress((void**)&fgl, g_fgl);
    cudaGetSymbolAddress((void**)&f3h, g_f3h);
    cudaGetSymbolAddress((void**)&f3l, g_f3l);
    float *p1s, *p1q, *bn1a, *bn1c, *p3s, *p3q, *bn3a, *bn3c, *fg2;
    cudaGetSymbolAddress((void**)&p1s, g_p1s);
    cudaGetSymbolAddress((void**)&p1q, g_p1q);
    cudaGetSymbolAddress((void**)&bn1a, g_bn1a);
    cudaGetSymbolAddress((void**)&bn1c, g_bn1c);
    cudaGetSymbolAddress((void**)&p3s, g_p3s);
    cudaGetSymbolAddress((void**)&p3q, g_p3q);
    cudaGetSymbolAddress((void**)&bn3a, g_bn3a);
    cudaGetSymbolAddress((void**)&bn3c, g_bn3c);
    cudaGetSymbolAddress((void**)&fg2, g_fg2);

    const int NW = C2 * C1 + C3 * C3 + C4 * C3;
    k_splitW<<<(NW + 255) / 256, 256>>>(W2, W3, W4);
    k_transposeWf<<<(CF * C4 + 255) / 256, 256>>>(Wf);
    k_conv1<<<nb, C1>>>(pg, W1, b1);
    k_stats<<<C1, 256>>>(p1s, p1q, gamma1, beta1, bn1a, bn1c, nb, C1, NPT);
    k_bnsplit<<<(M * C1 / 2 + 255) / 256, 256>>>(f1, bn1a, bn1c, f1h, f1l, C1 - 1, M * C1 / 2);

    // conv2: f2[M,256] = f1bn[M,128] x W2^T + b2  -> split output + fused fg max
    k_gemm<<<mtiles * (C2 / 64), 256, GEMM_SMEM>>>(f1h, f1l, C1, W2h, W2l, C1, b2, nullptr, 0,
                                                   nullptr, f2h, f2l, nullptr, fgh, fgl,
                                                   nullptr, nullptr, C2, C1 / KC, C2 / 64);

    // h[nb,512] = fg[nb,256] x W3[:,0:256]^T + b3  -> f32
    k_gemm<<<(nb / 128) * (C3 / 64), 256, GEMM_SMEM>>>(fgh, fgl, C2, W3h, W3l, C3, b3, nullptr, 0,
                                                       h, nullptr, nullptr, nullptr, nullptr,
                                                       nullptr, nullptr, nullptr, C3, C2 / KC, C3 / 64);

    // conv3: f3[M,512] = f2[M,256] x W3[:,256:512]^T + h[group] -> split output + fused BN partials
    k_gemm<<<mtiles * (C3 / 64), 256, GEMM_SMEM>>>(f2h, f2l, C2, W3h + C2, W3l + C2, C3, nullptr, h, C3,
                                                   nullptr, f3h, f3l, nullptr, nullptr, nullptr,
                                                   p3s, p3q, C3, C2 / KC, C3 / 64);

    k_stats<<<C3, 256>>>(p3s, p3q, gamma3, beta3, bn3a, bn3c, nb, C3, NPT);
    k_bnsplit2<<<(M * C3 / 2 + 255) / 256, 256>>>(f3h, f3l, bn3a, bn3c, C3 - 1, M * C3 / 2);

    // conv4: feat[M,384] = f3bn[M,512] x W4^T + b4  -> f32 + fused fg2 max
    k_gemm<<<mtiles * (C4 / 64), 256, GEMM_SMEM>>>(f3h, f3l, C3, W4h, W4l, C3, b4, nullptr, 0,
                                                   feat, nullptr, nullptr, fg2, nullptr, nullptr,
                                                   nullptr, nullptr, C4, C3 / KC, C4 / 64);

    k_knn<<<nb, C4, knn_smem>>>(pg);
    k_std<<<1, 256>>>(nb);
    k_fuse<<<nb, C4>>>(alpha, beta_af, bf);
    k_statsF<<<C4, 256>>>(gammaf, betaf, nb);
    k_out<<<(nb * C4 + 255) / 256, 256>>>((float*)d_out, nb * C4);
}

// round 13
// speedup vs baseline: 1.5364x; 1.0160x over previous
#include <cuda_runtime.h>
#include <cuda_bf16.h>
#include <cuda_fp16.h>
#include <math_constants.h>
#include <cstdint>

#define NPT 32
#define C1 128
#define C2 256
#define C3 512
#define C4 384
#define CF 768
#define KG 8
#define BMAX 1024
#define EPSF 1e-5f

// ---------------- scratch (device globals; no allocation) ----------------
__device__ float g_WfT[CF * C4];

__device__ float g_f1[BMAX * NPT * C1];
__device__ float g_p1s[BMAX * C1];
__device__ float g_p1q[BMAX * C1];
__device__ float g_bn1a[C1], g_bn1c[C1];

__device__ __half g_f1h[BMAX * NPT * C1], g_f1l[BMAX * NPT * C1];
__device__ __half g_W2h[C2 * C1], g_W2l[C2 * C1];
__device__ __half g_W3h[C3 * C3], g_W3l[C3 * C3];
__device__ __half g_W4h[C4 * C3], g_W4l[C4 * C3];

__device__ __half g_f2h[BMAX * NPT * C2], g_f2l[BMAX * NPT * C2];
__device__ __half g_fgh[BMAX * C2], g_fgl[BMAX * C2];
__device__ float g_h[BMAX * C3];

__device__ __half g_f3h[BMAX * NPT * C3], g_f3l[BMAX * NPT * C3];
__device__ float g_p3s[BMAX * C3];
__device__ float g_p3q[BMAX * C3];
__device__ float g_bn3a[C3], g_bn3c[C3];

__device__ float g_feat[BMAX * NPT * C4];
__device__ float g_fg2[BMAX * C4];

__device__ float g_mdx[BMAX * C4];
__device__ double g_p7[BMAX * 2];
__device__ float g_inv[1];

__device__ float g_y[BMAX * C4];
__device__ float g_bnFa[C4], g_bnFc[C4];

// ================= helpers =================
__device__ __forceinline__ uint32_t smem_u32(const void* p) {
    uint32_t a;
    asm("{ .reg .u64 t; cvta.to.shared.u64 t, %1; cvt.u32.u64 %0, t; }" : "=r"(a) : "l"(p));
    return a;
}
__device__ __forceinline__ void cp_async16(uint32_t dst, const void* src) {
    asm volatile("cp.async.cg.shared.global [%0], [%1], 16;" :: "r"(dst), "l"(src));
}
#define CP_COMMIT() asm volatile("cp.async.commit_group;" ::: "memory")
#define CP_WAIT1() asm volatile("cp.async.wait_group 1;" ::: "memory")
#define CP_WAIT0() asm volatile("cp.async.wait_group 0;" ::: "memory")

__device__ __forceinline__ void ldsm4(uint32_t* r, uint32_t addr) {
    asm volatile("ldmatrix.sync.aligned.m8n8.x4.shared.b16 {%0,%1,%2,%3}, [%4];"
                 : "=r"(r[0]), "=r"(r[1]), "=r"(r[2]), "=r"(r[3]) : "r"(addr));
}
__device__ __forceinline__ void mma_f16(float* d, const uint32_t* a, uint32_t b0, uint32_t b1) {
    asm volatile(
        "mma.sync.aligned.m16n8k16.row.col.f32.f16.f16.f32 "
        "{%0,%1,%2,%3}, {%4,%5,%6,%7}, {%8,%9}, {%0,%1,%2,%3};"
        : "+f"(d[0]), "+f"(d[1]), "+f"(d[2]), "+f"(d[3])
        : "r"(a[0]), "r"(a[1]), "r"(a[2]), "r"(a[3]), "r"(b0), "r"(b1));
}
__device__ __forceinline__ void splitf(float v, __half& h, __half& l) {
    h = __float2half_rn(v);
    l = __float2half_rn(v - __half2float(h));
}

// ================= fp16 pre-split GEMM (128x64 CTA tile, occupancy 2) =================
// out[M,Nt] = (Ah+Al)[M,K] * (Bh+Bl)[Nt,K]^T + bias + gadd (3-term fp16 MMA)
// 256 threads = 8 warps (4M x 2N), warp tile 32x32 -> each M-warp = one 32-row group.
// Optional fused per-group reductions (max, sum/sqsum).
#define KC 64
// stage layout (bytes): Ahi 0 (16K), Alo 16384, Bhi 32768 (8K), Blo 40960; 128B swizzled rows
#define STAGE_B 49152
#define GEMM_SMEM (2 * STAGE_B)

#define LOAD_CHUNK(kc, stg) do {                                   \
    uint32_t _b = sb + (uint32_t)(stg) * STAGE_B;                  \
    const __half* _ah = aSrcH + (size_t)(kc) * KC;                 \
    const __half* _al = aSrcL + (size_t)(kc) * KC;                 \
    const __half* _bh = bSrcH + (size_t)(kc) * KC;                 \
    const __half* _bl = bSrcL + (size_t)(kc) * KC;                 \
    _Pragma("unroll")                                              \
    for (int _j = 0; _j < 4; _j++) {                               \
        cp_async16(_b + dswA[_j], _ah + _j * 8);                   \
        cp_async16(_b + 16384 + dswA[_j], _al + _j * 8);           \
    }                                                              \
    _Pragma("unroll")                                              \
    for (int _j = 0; _j < 2; _j++) {                               \
        cp_async16(_b + 32768 + dswB[_j], _bh + _j * 32);          \
        cp_async16(_b + 40960 + dswB[_j], _bl + _j * 32);          \
    }                                                              \
    CP_COMMIT();                                                   \
} while (0)

__global__ void __launch_bounds__(256, 2) k_gemm(
    const __half* __restrict__ Ah, const __half* __restrict__ Al, int lda,
    const __half* __restrict__ Bh, const __half* __restrict__ Bl, int ldb,
    const float* __restrict__ bias, const float* __restrict__ gadd, int ldg,
    float* __restrict__ outF, __half* __restrict__ outH, __half* __restrict__ outL,
    float* __restrict__ maxF, __half* __restrict__ maxH, __half* __restrict__ maxL,
    float* __restrict__ statS, float* __restrict__ statQ,
    int ntotal, int nchunks, int ntiles) {
    extern __shared__ char smem[];
    uint32_t sb = smem_u32(smem);
    int t = threadIdx.x, wid = t >> 5, lane = t & 31;
    int gid = lane >> 2, tig = lane & 3;
    int mt = blockIdx.x / ntiles, nt = blockIdx.x % ntiles;
    int m0 = mt * 128, n0 = nt * 64;
    int warpM = (wid & 3) * 32, warpN = (wid >> 2) * 32;

    // A loader: thread t covers row t>>1, half (t&1) -> 4x16B per array
    int lrow = t >> 1;
    int lc = (t & 1) * 4;
    uint32_t dswA[4];
#pragma unroll
    for (int j = 0; j < 4; j++)
        dswA[j] = (uint32_t)lrow * 128 + (((uint32_t)(lc + j) * 16) ^ ((uint32_t)(lrow & 7) << 4));
    // B loader: thread t covers row t>>2, chunks {t&3, (t&3)+4}
    int brow = t >> 2, bj = t & 3;
    uint32_t dswB[2];
#pragma unroll
    for (int j = 0; j < 2; j++) {
        int cidx = bj + j * 4;
        dswB[j] = (uint32_t)brow * 128 + (((uint32_t)cidx * 16) ^ ((uint32_t)(brow & 7) << 4));
    }
    const __half* aSrcH = Ah + (size_t)(m0 + lrow) * lda + lc * 8;
    const __half* aSrcL = Al + (size_t)(m0 + lrow) * lda + lc * 8;
    const __half* bSrcH = Bh + (size_t)(n0 + brow) * ldb + bj * 8;
    const __half* bSrcL = Bl + (size_t)(n0 + brow) * ldb + bj * 8;

    // fragment addressing (byte-logical offset swizzle)
    uint32_t xorv = (uint32_t)(lane & 7) << 4;
    uint32_t aOff0 = (uint32_t)(warpM + (lane & 15)) * 128;
    uint32_t aOff1 = aOff0 + 16 * 128;
    uint32_t kselA = (uint32_t)(lane & 16);
    uint32_t kselB = (uint32_t)((lane & 8) << 1);
    uint32_t bOff[2];
#pragma unroll
    for (int np = 0; np < 2; np++)
        bOff[np] = (uint32_t)(warpN + np * 16 + (lane & 7) + ((lane & 16) >> 1)) * 128;

    LOAD_CHUNK(0, 0);

    float acc[2][4][4];
#pragma unroll
    for (int mi = 0; mi < 2; mi++)
#pragma unroll
        for (int ni = 0; ni < 4; ni++)
#pragma unroll
            for (int c = 0; c < 4; c++) acc[mi][ni][c] = 0.f;

    for (int kc = 0; kc < nchunks; kc++) {
        int p = kc & 1;
        if (kc + 1 < nchunks) {
            LOAD_CHUNK(kc + 1, p ^ 1);
            CP_WAIT1();
        } else {
            CP_WAIT0();
        }
        __syncthreads();
        uint32_t bA = sb + (uint32_t)p * STAGE_B;
#pragma unroll
        for (int ks = 0; ks < KC; ks += 16) {
            uint32_t offA = (((uint32_t)(2 * ks)) + kselA) ^ xorv;
            uint32_t offB = (((uint32_t)(2 * ks)) + kselB) ^ xorv;
            uint32_t ah0[4], ah1[4], al0[4], al1[4];
            ldsm4(ah0, bA + aOff0 + offA);
            ldsm4(ah1, bA + aOff1 + offA);
            ldsm4(al0, bA + 16384 + aOff0 + offA);
            ldsm4(al1, bA + 16384 + aOff1 + offA);
#pragma unroll
            for (int np = 0; np < 2; np++) {
                uint32_t bh[4], bl[4];
                ldsm4(bh, bA + 32768 + bOff[np] + offB);
                ldsm4(bl, bA + 40960 + bOff[np] + offB);
                mma_f16(acc[0][2 * np], ah0, bh[0], bh[1]);
                mma_f16(acc[1][2 * np], ah1, bh[0], bh[1]);
                mma_f16(acc[0][2 * np], ah0, bl[0], bl[1]);
                mma_f16(acc[1][2 * np], ah1, bl[0], bl[1]);
                mma_f16(acc[0][2 * np], al0, bh[0], bh[1]);
                mma_f16(acc[1][2 * np], al1, bh[0], bh[1]);
                mma_f16(acc[0][2 * np + 1], ah0, bh[2], bh[3]);
                mma_f16(acc[1][2 * np + 1], ah1, bh[2], bh[3]);
                mma_f16(acc[0][2 * np + 1], ah0, bl[2], bl[3]);
                mma_f16(acc[1][2 * np + 1], ah1, bl[2], bl[3]);
                mma_f16(acc[0][2 * np + 1], al0, bh[2], bh[3]);
                mma_f16(acc[1][2 * np + 1], al1, bh[2], bh[3]);
            }
        }
        __syncthreads();
    }

    // ---------- epilogue ----------
    int g = (m0 + warpM) >> 5;  // this M-warp's group (32 rows == 1 group)
    const float* grow = gadd ? (gadd + (size_t)g * ldg + n0) : nullptr;

    // main store
#pragma unroll
    for (int mi = 0; mi < 2; mi++) {
        int gm = m0 + warpM + mi * 16 + gid;
#pragma unroll
        for (int ni = 0; ni < 4; ni++) {
            int n = warpN + ni * 8 + 2 * tig;
            float add0 = 0.f, add1 = 0.f;
            if (bias) { add0 += bias[n0 + n]; add1 += bias[n0 + n + 1]; }
            if (grow) { add0 += grow[n]; add1 += grow[n + 1]; }
            float v00 = acc[mi][ni][0] + add0, v01 = acc[mi][ni][1] + add1;
            float v10 = acc[mi][ni][2] + add0, v11 = acc[mi][ni][3] + add1;
            if (outF) {
                *(float2*)(outF + (size_t)gm * ntotal + n0 + n) = make_float2(v00, v01);
                *(float2*)(outF + (size_t)(gm + 8) * ntotal + n0 + n) = make_float2(v10, v11);
            } else {
                __half h00, l00, h01, l01, h10, l10, h11, l11;
                splitf(v00, h00, l00); splitf(v01, h01, l01);
                splitf(v10, h10, l10); splitf(v11, h11, l11);
                *(__half2*)(outH + (size_t)gm * ntotal + n0 + n) = __halves2half2(h00, h01);
                *(__half2*)(outL + (size_t)gm * ntotal + n0 + n) = __halves2half2(l00, l01);
                *(__half2*)(outH + (size_t)(gm + 8) * ntotal + n0 + n) = __halves2half2(h10, h11);
                *(__half2*)(outL + (size_t)(gm + 8) * ntotal + n0 + n) = __halves2half2(l10, l11);
            }
        }
    }

    // fused per-group column max
    if (maxF || maxH) {
#pragma unroll
        for (int ni = 0; ni < 4; ni++) {
            int n = warpN + ni * 8 + 2 * tig;
            float mx0 = fmaxf(fmaxf(acc[0][ni][0], acc[0][ni][2]),
                              fmaxf(acc[1][ni][0], acc[1][ni][2]));
            float mx1 = fmaxf(fmaxf(acc[0][ni][1], acc[0][ni][3]),
                              fmaxf(acc[1][ni][1], acc[1][ni][3]));
#pragma unroll
            for (int m = 4; m <= 16; m <<= 1) {
                mx0 = fmaxf(mx0, __shfl_xor_sync(0xffffffffu, mx0, m));
                mx1 = fmaxf(mx1, __shfl_xor_sync(0xffffffffu, mx1, m));
            }
            if (gid == 0) {
                float add0 = bias ? bias[n0 + n] : 0.f;
                float add1 = bias ? bias[n0 + n + 1] : 0.f;
                float v0 = mx0 + add0, v1 = mx1 + add1;
                if (maxF) {
                    *(float2*)(maxF + (size_t)g * ntotal + n0 + n) = make_float2(v0, v1);
                } else {
                    __half h0, l0, h1, l1;
                    splitf(v0, h0, l0); splitf(v1, h1, l1);
                    *(__half2*)(maxH + (size_t)g * ntotal + n0 + n) = __halves2half2(h0, h1);
                    *(__half2*)(maxL + (size_t)g * ntotal + n0 + n) = __halves2half2(l0, l1);
                }
            }
        }
    }

    // fused per-group column sum / sqsum (for BN partials)
    if (statS) {
#pragma unroll
        for (int ni = 0; ni < 4; ni++) {
            int n = warpN + ni * 8 + 2 * tig;
            float add0 = 0.f, add1 = 0.f;
            if (bias) { add0 += bias[n0 + n]; add1 += bias[n0 + n + 1]; }
            if (grow) { add0 += grow[n]; add1 += grow[n + 1]; }
            float s0 = 0.f, q0 = 0.f, s1 = 0.f, q1 = 0.f;
#pragma unroll
            for (int mi = 0; mi < 2; mi++) {
                float v;
                v = acc[mi][ni][0] + add0; s0 += v; q0 = fmaf(v, v, q0);
                v = acc[mi][ni][2] + add0; s0 += v; q0 = fmaf(v, v, q0);
                v = acc[mi][ni][1] + add1; s1 += v; q1 = fmaf(v, v, q1);
                v = acc[mi][ni][3] + add1; s1 += v; q1 = fmaf(v, v, q1);
            }
#pragma unroll
            for (int m = 4; m <= 16; m <<= 1) {
                s0 += __shfl_xor_sync(0xffffffffu, s0, m);
                q0 += __shfl_xor_sync(0xffffffffu, q0, m);
                s1 += __shfl_xor_sync(0xffffffffu, s1, m);
                q1 += __shfl_xor_sync(0xffffffffu, q1, m);
            }
            if (gid == 0) {
                *(float2*)(statS + (size_t)g * ntotal + n0 + n) = make_float2(s0, s1);
                *(float2*)(statQ + (size_t)g * ntotal + n0 + n) = make_float2(q0, q1);
            }
        }
    }
}

// ---------------- weight split ----------------
__global__ void k_splitW(const float* __restrict__ W2, const float* __restrict__ W3,
                         const float* __restrict__ W4) {
    int i = blockIdx.x * blockDim.x + threadIdx.x;
    const int N2 = C2 * C1, N3 = C3 * C3, N4 = C4 * C3;
    float v; __half h, l;
    if (i < N2) {
        v = W2[i]; splitf(v, h, l); g_W2h[i] = h; g_W2l[i] = l;
    } else if (i < N2 + N3) {
        int j = i - N2; v = W3[j]; splitf(v, h, l); g_W3h[j] = h; g_W3l[j] = l;
    } else if (i < N2 + N3 + N4) {
        int j = i - N2 - N3; v = W4[j]; splitf(v, h, l); g_W4h[j] = h; g_W4l[j] = l;
    }
}

// ---------------- Wf transpose (for k_fuse coalescing) ----------------
__global__ void k_transposeWf(const float* __restrict__ Wf) {
    int i = blockIdx.x * blockDim.x + threadIdx.x;
    if (i < CF * C4) {
        int c = i / C4, o = i % C4;
        g_WfT[i] = Wf[o * CF + c];
    }
}

// ---------------- conv1: (B,32,3) -> raw f1 + per-b channel partials ----------------
__global__ void __launch_bounds__(C1) k_conv1(const float* __restrict__ pg,
                                              const float* __restrict__ W1,
                                              const float* __restrict__ b1) {
    int b = blockIdx.x;
    int o = threadIdx.x;
    __shared__ float sp[NPT * 3];
    for (int i = o; i < NPT * 3; i += C1) sp[i] = pg[b * NPT * 3 + i];
    __syncthreads();
    float w0 = W1[o * 3 + 0], w1 = W1[o * 3 + 1], w2 = W1[o * 3 + 2], bb = b1[o];
    float s = 0.f, q = 0.f;
#pragma unroll
    for (int l = 0; l < NPT; l++) {
        float v = fmaf(sp[l * 3 + 0], w0, fmaf(sp[l * 3 + 1], w1, fmaf(sp[l * 3 + 2], w2, bb)));
        g_f1[(b * NPT + l) * C1 + o] = v;
        s += v;
        q = fmaf(v, v, q);
    }
    g_p1s[b * C1 + o] = s;
    g_p1q[b * C1 + o] = q;
}

// ---------------- BN-stats reduce ----------------
__global__ void k_stats(const float* __restrict__ ps, const float* __restrict__ pq,
                        const float* __restrict__ gamma, const float* __restrict__ beta,
                        float* __restrict__ aout, float* __restrict__ cout,
                        int nb, int C, int perB) {
    int o = blockIdx.x;
    int t = threadIdx.x;
    double s = 0.0, q = 0.0;
    for (int b = t; b < nb; b += 256) {
        s += (double)ps[b * C + o];
        q += (double)pq[b * C + o];
    }
    __shared__ double sh[256], sh2[256];
    sh[t] = s; sh2[t] = q;
    __syncthreads();
    for (int st = 128; st > 0; st >>= 1) {
        if (t < st) { sh[t] += sh[t + st]; sh2[t] += sh2[t + st]; }
        __syncthreads();
    }
    if (t == 0) {
        double N = (double)nb * (double)perB;
        double mean = sh[0] / N;
        double var = sh2[0] / N - mean * mean;
        float a = gamma[o] * rsqrtf((float)var + EPSF);
        aout[o] = a;
        cout[o] = beta[o] - (float)mean * a;
    }
}

// ---------------- bn+relu+split: f32 in -> half pair out (2 elems/thread) ----------------
__global__ void k_bnsplit(const float* __restrict__ x, const float* __restrict__ a,
                          const float* __restrict__ c, __half* __restrict__ oh,
                          __half* __restrict__ ol, int cmask, int n2) {
    int i = blockIdx.x * blockDim.x + threadIdx.x;
    if (i < n2) {
        int j = 2 * i;
        int c0 = j & cmask, c1 = (j + 1) & cmask;
        float2 v = *(const float2*)(x + j);
        float u0 = fmaxf(fmaf(v.x, a[c0], c[c0]), 0.f);
        float u1 = fmaxf(fmaf(v.y, a[c1], c[c1]), 0.f);
        __half h0, l0, h1, l1;
        splitf(u0, h0, l0); splitf(u1, h1, l1);
        *(__half2*)(oh + j) = __halves2half2(h0, h1);
        *(__half2*)(ol + j) = __halves2half2(l0, l1);
    }
}

// ---------------- bn+relu+split in place on a half pair (8 elems/thread, 16B IO) ----------------
__global__ void k_bnsplit2(__half* __restrict__ xh, __half* __restrict__ xl,
                           const float* __restrict__ a, const float* __restrict__ c,
                           int cmask, int n8) {
    int i = blockIdx.x * blockDim.x + threadIdx.x;
    if (i < n8) {
        int j = 8 * i;
        int c0 = j & cmask;
        uint4 rh = *(uint4*)(xh + j);
        uint4 rl = *(uint4*)(xl + j);
        const __half2* ph = (const __half2*)&rh;
        const __half2* pl = (const __half2*)&rl;
        float4 a0 = *(const float4*)(a + c0);
        float4 a1 = *(const float4*)(a + c0 + 4);
        float4 b0 = *(const float4*)(c + c0);
        float4 b1 = *(const float4*)(c + c0 + 4);
        float aa[8] = {a0.x, a0.y, a0.z, a0.w, a1.x, a1.y, a1.z, a1.w};
        float bb[8] = {b0.x, b0.y, b0.z, b0.w, b1.x, b1.y, b1.z, b1.w};
        __half2 hh[4], ll[4];
#pragma unroll
        for (int k = 0; k < 4; k++) {
            float2 vh = __half22float2(ph[k]);
            float2 vl = __half22float2(pl[k]);
            float u0 = fmaxf(fmaf(vh.x + vl.x, aa[2 * k], bb[2 * k]), 0.f);
            float u1 = fmaxf(fmaf(vh.y + vl.y, aa[2 * k + 1], bb[2 * k + 1]), 0.f);
            __half h0, l0, h1, l1;
            splitf(u0, h0, l0);
            splitf(u1, h1, l1);
            hh[k] = __halves2half2(h0, h1);
            ll[k] = __halves2half2(l0, l1);
        }
        *(uint4*)(xh + j) = *(uint4*)hh;
        *(uint4*)(xl + j) = *(uint4*)ll;
    }
}

// ---------------- knn + dx statistics per group ----------------
__global__ void __launch_bounds__(C4) k_knn(const float* __restrict__ pgin) {
    extern __shared__ float sm[];
    float* ft = sm;                         // 32*384
    float* sp = ft + NPT * C4;              // 96
    float* sq = sp + NPT * 3;               // 32
    float* d = sq + NPT;                    // 1024
    int* sidx = (int*)(d + NPT * NPT);      // 256
    int b = blockIdx.x, t = threadIdx.x;
    for (int i = t; i < NPT * C4; i += C4) ft[i] = g_feat[(size_t)b * NPT * C4 + i];
    for (int i = t; i < NPT * 3; i += C4) sp[i] = pgin[b * NPT * 3 + i];
    __syncthreads();
    if (t < NPT) {
        float x = sp[t * 3], y = sp[t * 3 + 1], z = sp[t * 3 + 2];
        sq[t] = x * x + y * y + z * z;
    }
    __syncthreads();
    for (int i = t; i < NPT * NPT; i += C4) {
        int n = i / NPT, m = i % NPT;
        float dot = sp[n * 3] * sp[m * 3] + sp[n * 3 + 1] * sp[m * 3 + 1] + sp[n * 3 + 2] * sp[m * 3 + 2];
        d[i] = sq[n] + sq[m] - 2.f * dot;
    }
    __syncthreads();
    if (t < NPT) {
        unsigned chosen = 0;
        for (int k = 0; k < KG; k++) {
            float best = CUDART_INF_F;
            int bi = 0;
            for (int m = 0; m < NPT; m++) {
                if ((chosen >> m) & 1u) continue;
                float dv = d[t * NPT + m];
                if (dv < best) { best = dv; bi = m; }
            }
            chosen |= 1u << bi;
            sidx[t * KG + k] = bi;
        }
    }
    __syncthreads();
    int c = t;
    float chsum = 0.f, gq = 0.f;
#pragma unroll 4
    for (int p = 0; p < NPT * KG; p++) {
        int n = p >> 3;
        int j = sidx[p];
        float dx = ft[j * C4 + c] - ft[n * C4 + c];
        chsum += dx;
        gq = fmaf(dx, dx, gq);
    }
    g_mdx[b * C4 + c] = chsum * (1.f / (float)(NPT * KG));
    __syncthreads();
    float* r1 = d;
    float* r2 = d + 512;
    r1[t] = chsum; r2[t] = gq;
    __syncthreads();
    if (t < 128) {
        r1[t] += r1[t + 128] + r1[t + 256];
        r2[t] += r2[t + 128] + r2[t + 256];
    }
    __syncthreads();
    for (int st = 64; st > 0; st >>= 1) {
        if (t < st) { r1[t] += r1[t + st]; r2[t] += r2[t + st]; }
        __syncthreads();
    }
    if (t == 0) {
        g_p7[2 * b + 0] = (double)r1[0];
        g_p7[2 * b + 1] = (double)r2[0];
    }
}

// ---------------- global std (ddof=1) ----------------
__global__ void k_std(int nb) {
    int t = threadIdx.x;
    double s = 0.0, q = 0.0;
    for (int b = t; b < nb; b += 256) {
        s += g_p7[2 * b + 0];
        q += g_p7[2 * b + 1];
    }
    __shared__ double sh[256], sh2[256];
    sh[t] = s; sh2[t] = q;
    __syncthreads();
    for (int st = 128; st > 0; st >>= 1) {
        if (t < st) { sh[t] += sh[t + st]; sh2[t] += sh2[t + st]; }
        __syncthreads();
    }
    if (t == 0) {
        double N = (double)nb * NPT * KG * C4;
        double var = (sh2[0] - sh[0] * sh[0] / N) / (N - 1.0);
        float sd = sqrtf((float)var);
        g_inv[0] = 1.f / (sd + EPSF);
    }
}

// ---------------- fused layer GEMV (768 -> 384) ----------------
__global__ void __launch_bounds__(C4) k_fuse(const float* __restrict__ alpha,
                                             const float* __restrict__ beta_aff,
                                             const float* __restrict__ bf) {
    __shared__ float sin_[CF];
    int b = blockIdx.x, t = threadIdx.x;
    float inv = g_inv[0];
    sin_[t] = g_fg2[b * C4 + t];
    sin_[C4 + t] = fmaf(alpha[t] * inv, g_mdx[b * C4 + t], beta_aff[t]);
    __syncthreads();
    int o = t;
    float acc = bf[o];
    const float4* s4 = (const float4*)sin_;
    for (int c0 = 0; c0 < CF; c0 += 4) {
        float4 sv = s4[c0 >> 2];
        acc = fmaf(sv.x, g_WfT[(c0 + 0) * C4 + o], acc);
        acc = fmaf(sv.y, g_WfT[(c0 + 1) * C4 + o], acc);
        acc = fmaf(sv.z, g_WfT[(c0 + 2) * C4 + o], acc);
        acc = fmaf(sv.w, g_WfT[(c0 + 3) * C4 + o], acc);
    }
    g_y[b * C4 + o] = acc;
}

// ---------------- final BN stats over y ----------------
__global__ void k_statsF(const float* __restrict__ gamma, const float* __restrict__ beta, int nb) {
    int o = blockIdx.x, t = threadIdx.x;
    double s = 0.0, q = 0.0;
    for (int b = t; b < nb; b += 256) {
        double v = (double)g_y[b * C4 + o];
        s += v; q += v * v;
    }
    __shared__ double sh[256], sh2[256];
    sh[t] = s; sh2[t] = q;
    __syncthreads();
    for (int st = 128; st > 0; st >>= 1) {
        if (t < st) { sh[t] += sh[t + st]; sh2[t] += sh2[t + st]; }
        __syncthreads();
    }
    if (t == 0) {
        double N = (double)nb;
        double mean = sh[0] / N;
        double var = sh2[0] / N - mean * mean;
        float a = gamma[o] * rsqrtf((float)var + EPSF);
        g_bnFa[o] = a;
        g_bnFc[o] = beta[o] - (float)mean * a;
    }
}

// ---------------- final apply ----------------
__global__ void k_out(float* __restrict__ out, int n) {
    int i = blockIdx.x * blockDim.x + threadIdx.x;
    if (i < n) {
        int o = i % C4;
        out[i] = fmaxf(fmaf(g_y[i], g_bnFa[o], g_bnFc[o]), 0.f);
    }
}

// ---------------- launch ----------------
extern "C" void kernel_launch(void* const* d_in, const int* in_sizes, int n_in,
                              void* d_out, int out_size) {
    const float* pg      = (const float*)d_in[0];
    const float* W1      = (const float*)d_in[1];
    const float* b1      = (const float*)d_in[2];
    const float* gamma1  = (const float*)d_in[3];
    const float* beta1   = (const float*)d_in[4];
    const float* W2      = (const float*)d_in[5];
    const float* b2      = (const float*)d_in[6];
    const float* W3      = (const float*)d_in[7];
    const float* b3      = (const float*)d_in[8];
    const float* gamma3  = (const float*)d_in[9];
    const float* beta3   = (const float*)d_in[10];
    const float* W4      = (const float*)d_in[11];
    const float* b4      = (const float*)d_in[12];
    const float* alpha   = (const float*)d_in[13];
    const float* beta_af = (const float*)d_in[14];
    const float* Wf      = (const float*)d_in[15];
    const float* bf      = (const float*)d_in[16];
    const float* gammaf  = (const float*)d_in[17];
    const float* betaf   = (const float*)d_in[18];

    int nb = in_sizes[0] / (NPT * 3);   // 1024
    int M = nb * NPT;                   // 32768
    int mtiles = M / 128;               // 256

    int knn_smem = (NPT * C4 + NPT * 3 + NPT + NPT * NPT) * 4 + NPT * KG * 4;
    cudaFuncSetAttribute(k_knn, cudaFuncAttributeMaxDynamicSharedMemorySize, knn_smem);
    cudaFuncSetAttribute(k_gemm, cudaFuncAttributeMaxDynamicSharedMemorySize, GEMM_SMEM);

    float *f1, *feat, *h;
    cudaGetSymbolAddress((void**)&f1, g_f1);
    cudaGetSymbolAddress((void**)&feat, g_feat);
    cudaGetSymbolAddress((void**)&h, g_h);
    __half *f1h, *f1l, *W2h, *W2l, *W3h, *W3l, *W4h, *W4l, *f2h, *f2l, *fgh, *fgl, *f3h, *f3l;
    cudaGetSymbolAddress((void**)&f1h, g_f1h);
    cudaGetSymbolAddress((void**)&f1l, g_f1l);
    cudaGetSymbolAddress((void**)&W2h, g_W2h);
    cudaGetSymbolAddress((void**)&W2l, g_W2l);
    cudaGetSymbolAddress((void**)&W3h, g_W3h);
    cudaGetSymbolAddress((void**)&W3l, g_W3l);
    cudaGetSymbolAddress((void**)&W4h, g_W4h);
    cudaGetSymbolAddress((void**)&W4l, g_W4l);
    cudaGetSymbolAddress((void**)&f2h, g_f2h);
    cudaGetSymbolAddress((void**)&f2l, g_f2l);
    cudaGetSymbolAddress((void**)&fgh, g_fgh);
    cudaGetSymbolAddress((void**)&fgl, g_fgl);
    cudaGetSymbolAddress((void**)&f3h, g_f3h);
    cudaGetSymbolAddress((void**)&f3l, g_f3l);
    float *p1s, *p1q, *bn1a, *bn1c, *p3s, *p3q, *bn3a, *bn3c, *fg2;
    cudaGetSymbolAddress((void**)&p1s, g_p1s);
    cudaGetSymbolAddress((void**)&p1q, g_p1q);
    cudaGetSymbolAddress((void**)&bn1a, g_bn1a);
    cudaGetSymbolAddress((void**)&bn1c, g_bn1c);
    cudaGetSymbolAddress((void**)&p3s, g_p3s);
    cudaGetSymbolAddress((void**)&p3q, g_p3q);
    cudaGetSymbolAddress((void**)&bn3a, g_bn3a);
    cudaGetSymbolAddress((void**)&bn3c, g_bn3c);
    cudaGetSymbolAddress((void**)&fg2, g_fg2);

    const int NW = C2 * C1 + C3 * C3 + C4 * C3;
    k_splitW<<<(NW + 255) / 256, 256>>>(W2, W3, W4);
    k_transposeWf<<<(CF * C4 + 255) / 256, 256>>>(Wf);
    k_conv1<<<nb, C1>>>(pg, W1, b1);
    k_stats<<<C1, 256>>>(p1s, p1q, gamma1, beta1, bn1a, bn1c, nb, C1, NPT);
    k_bnsplit<<<(M * C1 / 2 + 255) / 256, 256>>>(f1, bn1a, bn1c, f1h, f1l, C1 - 1, M * C1 / 2);

    // conv2: f2[M,256] = f1bn[M,128] x W2^T + b2  -> split output + fused fg max
    k_gemm<<<mtiles * (C2 / 64), 256, GEMM_SMEM>>>(f1h, f1l, C1, W2h, W2l, C1, b2, nullptr, 0,
                                                   nullptr, f2h, f2l, nullptr, fgh, fgl,
                                                   nullptr, nullptr, C2, C1 / KC, C2 / 64);

    // h[nb,512] = fg[nb,256] x W3[:,0:256]^T + b3  -> f32
    k_gemm<<<(nb / 128) * (C3 / 64), 256, GEMM_SMEM>>>(fgh, fgl, C2, W3h, W3l, C3, b3, nullptr, 0,
                                                       h, nullptr, nullptr, nullptr, nullptr,
                                                       nullptr, nullptr, nullptr, C3, C2 / KC, C3 / 64);

    // conv3: f3[M,512] = f2[M,256] x W3[:,256:512]^T + h[group] -> split output + fused BN partials
    k_gemm<<<mtiles * (C3 / 64), 256, GEMM_SMEM>>>(f2h, f2l, C2, W3h + C2, W3l + C2, C3, nullptr, h, C3,
                                                   nullptr, f3h, f3l, nullptr, nullptr, nullptr,
                                                   p3s, p3q, C3, C2 / KC, C3 / 64);

    k_stats<<<C3, 256>>>(p3s, p3q, gamma3, beta3, bn3a, bn3c, nb, C3, NPT);
    k_bnsplit2<<<(M * C3 / 8 + 255) / 256, 256>>>(f3h, f3l, bn3a, bn3c, C3 - 1, M * C3 / 8);

    // conv4: feat[M,384] = f3bn[M,512] x W4^T + b4  -> f32 + fused fg2 max
    k_gemm<<<mtiles * (C4 / 64), 256, GEMM_SMEM>>>(f3h, f3l, C3, W4h, W4l, C3, b4, nullptr, 0,
                                                   feat, nullptr, nullptr, fg2, nullptr, nullptr,
                                                   nullptr, nullptr, C4, C3 / KC, C4 / 64);

    k_knn<<<nb, C4, knn_smem>>>(pg);
    k_std<<<1, 256>>>(nb);
    k_fuse<<<nb, C4>>>(alpha, beta_af, bf);
    k_statsF<<<C4, 256>>>(gammaf, betaf, nb);
    k_out<<<(nb * C4 + 255) / 256, 256>>>((float*)d_out, nb * C4);
}